// round 4
// baseline (speedup 1.0000x reference)
#include <cuda_runtime.h>
#include <math.h>

#define N_TOK 4096
#define D_MODEL 320
#define HEADS 8
#define DH 40
#define SCALE 0.15811388300841897f  // 40^-0.5
#define NEG_BIG  (-3.0e38f)
#define M_INIT   (-1.0e37f)

// ---------------- scratch (no allocs allowed) ----------------
__device__ float g_Q[N_TOK * D_MODEL];
__device__ float g_K[N_TOK * D_MODEL];
__device__ float g_V[N_TOK * D_MODEL];
__device__ float g_A[N_TOK * D_MODEL];
__device__ int   g_code[N_TOK];
__device__ float g_vmean[D_MODEL];
__device__ float g_part[32 * D_MODEL];
__device__ int   g_klist[7 * N_TOK];
__device__ int   g_kcount[7];
__device__ int   g_qlist[7 * N_TOK];
__device__ int   g_qcount[7];

// ---------------- cp.async helpers ----------------
__device__ __forceinline__ void cp_async16(void* smem, const void* gmem) {
    unsigned sa = (unsigned)__cvta_generic_to_shared(smem);
    asm volatile("cp.async.cg.shared.global [%0], [%1], 16;" :: "r"(sa), "l"(gmem));
}
__device__ __forceinline__ void cp_commit() {
    asm volatile("cp.async.commit_group;");
}
template<int N> __device__ __forceinline__ void cp_wait() {
    asm volatile("cp.async.wait_group %0;" :: "n"(N));
}

// ---------------- phase-code kernel ----------------
__global__ void code_kernel(const float* __restrict__ g, int* __restrict__ code) {
    int i = blockIdx.x * 256 + threadIdx.x;
    if (i < N_TOK) {
        int c = 0;
        if (g[i]           > 0.5f) c |= 1;
        if (g[N_TOK + i]   > 0.5f) c |= 2;
        if (g[2*N_TOK + i] > 0.5f) c |= 4;
        code[i] = c;
    }
}

// ---------------- deterministic per-class list compaction (ballot scan) ----------------
__global__ __launch_bounds__(256) void build_lists(
    const int* __restrict__ code,
    int* __restrict__ klist, int* __restrict__ kcount,
    int* __restrict__ qlist, int* __restrict__ qcount)
{
    int c = blockIdx.x + 1;
    int tid = threadIdx.x;
    int lane = tid & 31, wid = tid >> 5;
    __shared__ int wk[8], wq[8];
    __shared__ int kbase, qbase;
    if (tid == 0) { kbase = 0; qbase = 0; }
    __syncthreads();

    int loff = (c - 1) * N_TOK;
    for (int t0 = 0; t0 < N_TOK; t0 += 256) {
        int i = t0 + tid;
        int ci = code[i];
        int kp = (ci & c) ? 1 : 0;
        int qp = (ci == c) ? 1 : 0;

        unsigned kb = __ballot_sync(0xffffffffu, kp);
        unsigned qb = __ballot_sync(0xffffffffu, qp);
        int kpre = __popc(kb & ((1u << lane) - 1));
        int qpre = __popc(qb & ((1u << lane) - 1));
        if (lane == 0) { wk[wid] = __popc(kb); wq[wid] = __popc(qb); }
        __syncthreads();
        if (tid == 0) {
            int rk = kbase, rq = qbase;
            #pragma unroll
            for (int w = 0; w < 8; ++w) {
                int tk = wk[w]; wk[w] = rk; rk += tk;
                int tq = wq[w]; wq[w] = rq; rq += tq;
            }
            kbase = rk; qbase = rq;
        }
        __syncthreads();
        if (kp) klist[loff + wk[wid] + kpre] = i;
        if (qp) qlist[loff + wq[wid] + qpre] = i;
        __syncthreads();
    }
    if (tid == 0) { kcount[c - 1] = kbase; qcount[c - 1] = qbase; }
}

// ---------------- coalesced 2-stage column mean of V ----------------
__global__ void vmean1(const float* __restrict__ V, float* __restrict__ part) {
    int b = blockIdx.x;           // 32 blocks, 128 rows each
    int c = threadIdx.x;          // 320 threads = columns
    float s = 0.f;
    int r0 = b * 128;
    #pragma unroll 4
    for (int r = 0; r < 128; ++r) s += V[(r0 + r) * D_MODEL + c];
    part[b * D_MODEL + c] = s;
}
__global__ void vmean2(const float* __restrict__ part, float* __restrict__ vm) {
    int c = threadIdx.x;
    float s = 0.f;
    #pragma unroll
    for (int b = 0; b < 32; ++b) s += part[b * D_MODEL + c];
    vm[c] = s * (1.f / (float)N_TOK);
}

// ---------------- fully-masked rows -> vmean ----------------
__global__ void fill_inactive(const int* __restrict__ code,
                              const float* __restrict__ vmean,
                              float* __restrict__ A) {
    int row = blockIdx.x;
    if (code[row] != 0) return;
    for (int d = threadIdx.x; d < D_MODEL; d += 64)
        A[row * D_MODEL + d] = vmean[d];
}

// ---------------- tiled fp32 GEMM body ----------------
__device__ __forceinline__ void gemm64_body(
    const float* __restrict__ A, const float* __restrict__ B,
    const float* __restrict__ bias, float* __restrict__ C,
    int M, int N, int K, int m0, int n0)
{
    __shared__ float As[16][68];
    __shared__ float Bs[16][68];
    int tid = threadIdx.x;
    int ty = tid >> 4, tx = tid & 15;

    int lr = tid >> 2;
    int lk = (tid & 3) * 4;
    int bk = tid >> 4;
    int bc = (tid & 15) * 4;

    float acc[4][4];
    #pragma unroll
    for (int i = 0; i < 4; ++i)
        #pragma unroll
        for (int j = 0; j < 4; ++j) acc[i][j] = 0.f;

    for (int k0 = 0; k0 < K; k0 += 16) {
        float4 av = *(const float4*)&A[(m0 + lr) * K + k0 + lk];
        As[lk + 0][lr] = av.x; As[lk + 1][lr] = av.y;
        As[lk + 2][lr] = av.z; As[lk + 3][lr] = av.w;
        float4 bv = *(const float4*)&B[(k0 + bk) * N + n0 + bc];
        *(float4*)&Bs[bk][bc] = bv;
        __syncthreads();
        #pragma unroll
        for (int kk = 0; kk < 16; ++kk) {
            float a[4], b[4];
            #pragma unroll
            for (int i = 0; i < 4; ++i) a[i] = As[kk][ty * 4 + i];
            #pragma unroll
            for (int j = 0; j < 4; ++j) b[j] = Bs[kk][tx * 4 + j];
            #pragma unroll
            for (int i = 0; i < 4; ++i)
                #pragma unroll
                for (int j = 0; j < 4; ++j)
                    acc[i][j] = fmaf(a[i], b[j], acc[i][j]);
        }
        __syncthreads();
    }
    #pragma unroll
    for (int i = 0; i < 4; ++i) {
        int row = m0 + ty * 4 + i;
        #pragma unroll
        for (int j = 0; j < 4; ++j) {
            int col = n0 + tx * 4 + j;
            float v = acc[i][j];
            if (bias) v += bias[col];
            C[row * N + col] = v;
        }
    }
}

__global__ __launch_bounds__(256) void gemm64(
    const float* __restrict__ A, const float* __restrict__ B,
    const float* __restrict__ bias, float* __restrict__ C,
    int M, int N, int K)
{
    gemm64_body(A, B, bias, C, M, N, K, blockIdx.y * 64, blockIdx.x * 64);
}

__global__ __launch_bounds__(256) void gemm64_qkv(
    const float* __restrict__ A,
    const float* __restrict__ Wq, const float* __restrict__ Wk,
    const float* __restrict__ Wv,
    float* __restrict__ Q, float* __restrict__ K, float* __restrict__ V)
{
    const float* B = (blockIdx.z == 0) ? Wq : (blockIdx.z == 1) ? Wk : Wv;
    float* C = (blockIdx.z == 0) ? Q : (blockIdx.z == 1) ? K : V;
    gemm64_body(A, B, nullptr, C, N_TOK, D_MODEL, D_MODEL,
                blockIdx.y * 64, blockIdx.x * 64);
}

// ---------------- class-compacted flash attention, dim-split lanes ----------------
// 256 threads = 64 row-groups... lanes = 8 rows x 4 dim-quarters per warp.
// Each lane holds q[10], O[10]; dots reduced via 2x shfl.xor within 4-lane cluster.
// cp.async double-buffered K/V gather; 8-key chunks with one rescale per chunk.
__global__ __launch_bounds__(256) void attn_kernel(
    const float* __restrict__ Q, const float* __restrict__ Km,
    const float* __restrict__ Vm,
    const int* __restrict__ klist, const int* __restrict__ kcount,
    const int* __restrict__ qlist, const int* __restrict__ qcount,
    float* __restrict__ out)
{
    int grpIdx = blockIdx.x >> 6;
    int cls = (0x3105426 >> (grpIdx * 4)) & 7;   // heavy classes scheduled first
    int qt  = blockIdx.x & 63;
    int h   = blockIdx.y;
    int nQ = qcount[cls];
    if (qt * 64 >= nQ) return;
    int nK = kcount[cls];

    int tid = threadIdx.x;
    int grp = tid >> 2, lane4 = tid & 3;
    int qslot = qt * 64 + grp;
    bool valid = qslot < nQ;
    int row = valid ? qlist[cls * N_TOK + qslot] : qlist[cls * N_TOK];
    int hoff = h * DH;
    int dq = lane4 * 10;

    __shared__ float Ksm[2][64 * DH];
    __shared__ float Vsm[2][64 * DH];

    // q quarter: 10 floats (8B aligned)
    float q[10];
    {
        const float2* qp = (const float2*)&Q[row * D_MODEL + hoff + dq];
        #pragma unroll
        for (int i = 0; i < 5; ++i) { float2 t = qp[i]; q[2*i] = t.x; q[2*i+1] = t.y; }
    }

    float m = M_INIT, l = 0.f;
    float O[10];
    #pragma unroll
    for (int d = 0; d < 10; ++d) O[d] = 0.f;

    const int* kl = klist + cls * N_TOK;
    int ntiles = (nK + 63) >> 6;

    // prefetch tile 0
    {
        int nloc = nK < 64 ? nK : 64;
        for (int v2 = tid; v2 < 640; v2 += 256) {
            int r = v2 / 10, d4 = v2 - r * 10;
            if (r < nloc) {
                int j = kl[r];
                const float* src = Km + j * D_MODEL + hoff + d4 * 4;
                cp_async16(&Ksm[0][r * DH + d4 * 4], src);
                cp_async16(&Vsm[0][r * DH + d4 * 4], Vm + j * D_MODEL + hoff + d4 * 4);
            }
        }
        cp_commit();
    }

    for (int kt = 0; kt < ntiles; ++kt) {
        int buf = kt & 1;
        int base = kt << 6;
        int nloc = nK - base; if (nloc > 64) nloc = 64;

        if (kt + 1 < ntiles) {
            int base2 = base + 64;
            int nloc2 = nK - base2; if (nloc2 > 64) nloc2 = 64;
            float* Kb2 = Ksm[buf ^ 1];
            float* Vb2 = Vsm[buf ^ 1];
            for (int v2 = tid; v2 < 640; v2 += 256) {
                int r = v2 / 10, d4 = v2 - r * 10;
                if (r < nloc2) {
                    int j = kl[base2 + r];
                    cp_async16(&Kb2[r * DH + d4 * 4], Km + j * D_MODEL + hoff + d4 * 4);
                    cp_async16(&Vb2[r * DH + d4 * 4], Vm + j * D_MODEL + hoff + d4 * 4);
                }
            }
            cp_commit();
            cp_wait<1>();
        } else {
            cp_wait<0>();
        }
        __syncthreads();

        const float* Kb = Ksm[buf];
        const float* Vb = Vsm[buf];

        #pragma unroll 1
        for (int ch = 0; ch < 8; ++ch) {
            int j0 = ch << 3;
            float sc[8];
            #pragma unroll
            for (int s = 0; s < 8; ++s) {
                int j = j0 + s;
                const float2* kp = (const float2*)(Kb + j * DH + dq);
                float d = 0.f;
                #pragma unroll
                for (int i = 0; i < 5; ++i) {
                    float2 kk = kp[i];
                    d = fmaf(q[2*i], kk.x, d);
                    d = fmaf(q[2*i+1], kk.y, d);
                }
                d += __shfl_xor_sync(0xffffffffu, d, 1);
                d += __shfl_xor_sync(0xffffffffu, d, 2);
                sc[s] = (j < nloc) ? d * SCALE : NEG_BIG;
            }
            float tmax = sc[0];
            #pragma unroll
            for (int s = 1; s < 8; ++s) tmax = fmaxf(tmax, sc[s]);
            float mn = fmaxf(m, tmax);
            float f = __expf(m - mn);
            m = mn;
            l *= f;
            #pragma unroll
            for (int d = 0; d < 10; ++d) O[d] *= f;
            #pragma unroll
            for (int s = 0; s < 8; ++s) {
                float p = __expf(sc[s] - m);
                l += p;
                const float2* vp = (const float2*)(Vb + (j0 + s) * DH + dq);
                #pragma unroll
                for (int i = 0; i < 5; ++i) {
                    float2 vv = vp[i];
                    O[2*i]   = fmaf(p, vv.x, O[2*i]);
                    O[2*i+1] = fmaf(p, vv.y, O[2*i+1]);
                }
            }
        }
        __syncthreads();
    }

    if (valid) {
        float inv = 1.f / l;
        float* op = &out[row * D_MODEL + hoff + dq];
        #pragma unroll
        for (int i = 0; i < 5; ++i) {
            float2 t; t.x = O[2*i] * inv; t.y = O[2*i+1] * inv;
            *(float2*)(op + 2*i) = t;
        }
    }
}

extern "C" void kernel_launch(void* const* d_in, const int* in_sizes, int n_in,
                              void* d_out, int out_size) {
    const float* x     = (const float*)d_in[0];
    const float* gmask = (const float*)d_in[1];
    const float* Wq    = (const float*)d_in[2];
    const float* Wk    = (const float*)d_in[3];
    const float* Wv    = (const float*)d_in[4];
    const float* Wo    = (const float*)d_in[5];
    const float* bo    = (const float*)d_in[6];
    float* out = (float*)d_out;

    float *Qp, *Kp, *Vp, *Ap, *vmp, *pp; int *cp, *klp, *kcp, *qlp, *qcp;
    cudaGetSymbolAddress((void**)&Qp, g_Q);
    cudaGetSymbolAddress((void**)&Kp, g_K);
    cudaGetSymbolAddress((void**)&Vp, g_V);
    cudaGetSymbolAddress((void**)&Ap, g_A);
    cudaGetSymbolAddress((void**)&vmp, g_vmean);
    cudaGetSymbolAddress((void**)&pp, g_part);
    cudaGetSymbolAddress((void**)&cp, g_code);
    cudaGetSymbolAddress((void**)&klp, g_klist);
    cudaGetSymbolAddress((void**)&kcp, g_kcount);
    cudaGetSymbolAddress((void**)&qlp, g_qlist);
    cudaGetSymbolAddress((void**)&qcp, g_qcount);

    code_kernel<<<16, 256>>>(gmask, cp);
    build_lists<<<7, 256>>>(cp, klp, kcp, qlp, qcp);
    gemm64_qkv<<<dim3(D_MODEL / 64, N_TOK / 64, 3), 256>>>(x, Wq, Wk, Wv, Qp, Kp, Vp);
    attn_kernel<<<dim3(7 * 64, HEADS), 256>>>(Qp, Kp, Vp, klp, kcp, qlp, qcp, Ap);
    vmean1<<<32, 320>>>(Vp, pp);
    vmean2<<<1, 320>>>(pp, vmp);
    fill_inactive<<<N_TOK, 64>>>(cp, vmp, Ap);
    gemm64<<<dim3(D_MODEL / 64, N_TOK / 64), 256>>>(Ap, Wo, bo, out, N_TOK, D_MODEL, D_MODEL);
}

// round 7
// speedup vs baseline: 1.4506x; 1.4506x over previous
#include <cuda_runtime.h>
#include <math.h>

#define N_TOK 4096
#define D_MODEL 320
#define HEADS 8
#define DH 40
#define SCALE 0.15811388300841897f  // 40^-0.5
#define NEG_BIG  (-3.0e38f)
#define M_INIT   (-1.0e37f)

// ---------------- scratch (no allocs allowed) ----------------
__device__ float g_Q[N_TOK * D_MODEL];
__device__ float g_K[N_TOK * D_MODEL];
__device__ float g_V[N_TOK * D_MODEL];
__device__ float g_A[N_TOK * D_MODEL];
__device__ int   g_code[N_TOK];
__device__ float g_vmean[D_MODEL];
__device__ float g_part[32 * D_MODEL];
__device__ int   g_klist[7 * N_TOK];
__device__ int   g_kcount[7];
__device__ int   g_qlist[7 * N_TOK];
__device__ int   g_qcount[7];

// ---------------- cp.async helpers ----------------
__device__ __forceinline__ void cp_async16(void* smem, const void* gmem) {
    unsigned sa = (unsigned)__cvta_generic_to_shared(smem);
    asm volatile("cp.async.cg.shared.global [%0], [%1], 16;" :: "r"(sa), "l"(gmem));
}
__device__ __forceinline__ void cp_commit() {
    asm volatile("cp.async.commit_group;");
}
template<int N> __device__ __forceinline__ void cp_wait() {
    asm volatile("cp.async.wait_group %0;" :: "n"(N));
}

// ---------------- phase-code kernel ----------------
__global__ void code_kernel(const float* __restrict__ g, int* __restrict__ code) {
    int i = blockIdx.x * 256 + threadIdx.x;
    if (i < N_TOK) {
        int c = 0;
        if (g[i]           > 0.5f) c |= 1;
        if (g[N_TOK + i]   > 0.5f) c |= 2;
        if (g[2*N_TOK + i] > 0.5f) c |= 4;
        code[i] = c;
    }
}

// ---------------- deterministic per-class list compaction (ballot scan) ----------------
__global__ __launch_bounds__(256) void build_lists(
    const int* __restrict__ code,
    int* __restrict__ klist, int* __restrict__ kcount,
    int* __restrict__ qlist, int* __restrict__ qcount)
{
    int c = blockIdx.x + 1;
    int tid = threadIdx.x;
    int lane = tid & 31, wid = tid >> 5;
    __shared__ int wk[8], wq[8];
    __shared__ int kbase, qbase;
    if (tid == 0) { kbase = 0; qbase = 0; }
    __syncthreads();

    int loff = (c - 1) * N_TOK;
    for (int t0 = 0; t0 < N_TOK; t0 += 256) {
        int i = t0 + tid;
        int ci = code[i];
        int kp = (ci & c) ? 1 : 0;
        int qp = (ci == c) ? 1 : 0;

        unsigned kb = __ballot_sync(0xffffffffu, kp);
        unsigned qb = __ballot_sync(0xffffffffu, qp);
        int kpre = __popc(kb & ((1u << lane) - 1));
        int qpre = __popc(qb & ((1u << lane) - 1));
        if (lane == 0) { wk[wid] = __popc(kb); wq[wid] = __popc(qb); }
        __syncthreads();
        if (tid == 0) {
            int rk = kbase, rq = qbase;
            #pragma unroll
            for (int w = 0; w < 8; ++w) {
                int tk = wk[w]; wk[w] = rk; rk += tk;
                int tq = wq[w]; wq[w] = rq; rq += tq;
            }
            kbase = rk; qbase = rq;
        }
        __syncthreads();
        if (kp) klist[loff + wk[wid] + kpre] = i;
        if (qp) qlist[loff + wq[wid] + qpre] = i;
        __syncthreads();
    }
    if (tid == 0) { kcount[c - 1] = kbase; qcount[c - 1] = qbase; }
}

// ---------------- coalesced 2-stage column mean of V ----------------
__global__ void vmean1(const float* __restrict__ V, float* __restrict__ part) {
    int b = blockIdx.x;
    int c = threadIdx.x;
    float s = 0.f;
    int r0 = b * 128;
    #pragma unroll 4
    for (int r = 0; r < 128; ++r) s += V[(r0 + r) * D_MODEL + c];
    part[b * D_MODEL + c] = s;
}
__global__ void vmean2(const float* __restrict__ part, float* __restrict__ vm) {
    int c = threadIdx.x;
    float s = 0.f;
    #pragma unroll
    for (int b = 0; b < 32; ++b) s += part[b * D_MODEL + c];
    vm[c] = s * (1.f / (float)N_TOK);
}

// ---------------- fully-masked rows -> vmean ----------------
__global__ void fill_inactive(const int* __restrict__ code,
                              const float* __restrict__ vmean,
                              float* __restrict__ A) {
    int row = blockIdx.x;
    if (code[row] != 0) return;
    for (int d = threadIdx.x; d < D_MODEL; d += 64)
        A[row * D_MODEL + d] = vmean[d];
}

// ---------------- tiled fp32 GEMM body ----------------
__device__ __forceinline__ void gemm64_body(
    const float* __restrict__ A, const float* __restrict__ B,
    const float* __restrict__ bias, float* __restrict__ C,
    int M, int N, int K, int m0, int n0)
{
    __shared__ float As[16][68];
    __shared__ float Bs[16][68];
    int tid = threadIdx.x;
    int ty = tid >> 4, tx = tid & 15;

    int lr = tid >> 2;
    int lk = (tid & 3) * 4;
    int bk = tid >> 4;
    int bc = (tid & 15) * 4;

    float acc[4][4];
    #pragma unroll
    for (int i = 0; i < 4; ++i)
        #pragma unroll
        for (int j = 0; j < 4; ++j) acc[i][j] = 0.f;

    for (int k0 = 0; k0 < K; k0 += 16) {
        float4 av = *(const float4*)&A[(m0 + lr) * K + k0 + lk];
        As[lk + 0][lr] = av.x; As[lk + 1][lr] = av.y;
        As[lk + 2][lr] = av.z; As[lk + 3][lr] = av.w;
        float4 bv = *(const float4*)&B[(k0 + bk) * N + n0 + bc];
        *(float4*)&Bs[bk][bc] = bv;
        __syncthreads();
        #pragma unroll
        for (int kk = 0; kk < 16; ++kk) {
            float a[4], b[4];
            #pragma unroll
            for (int i = 0; i < 4; ++i) a[i] = As[kk][ty * 4 + i];
            #pragma unroll
            for (int j = 0; j < 4; ++j) b[j] = Bs[kk][tx * 4 + j];
            #pragma unroll
            for (int i = 0; i < 4; ++i)
                #pragma unroll
                for (int j = 0; j < 4; ++j)
                    acc[i][j] = fmaf(a[i], b[j], acc[i][j]);
        }
        __syncthreads();
    }
    #pragma unroll
    for (int i = 0; i < 4; ++i) {
        int row = m0 + ty * 4 + i;
        #pragma unroll
        for (int j = 0; j < 4; ++j) {
            int col = n0 + tx * 4 + j;
            float v = acc[i][j];
            if (bias) v += bias[col];
            C[row * N + col] = v;
        }
    }
}

__global__ __launch_bounds__(256) void gemm64(
    const float* __restrict__ A, const float* __restrict__ B,
    const float* __restrict__ bias, float* __restrict__ C,
    int M, int N, int K)
{
    gemm64_body(A, B, bias, C, M, N, K, blockIdx.y * 64, blockIdx.x * 64);
}

__global__ __launch_bounds__(256) void gemm64_qkv(
    const float* __restrict__ A,
    const float* __restrict__ Wq, const float* __restrict__ Wk,
    const float* __restrict__ Wv,
    float* __restrict__ Q, float* __restrict__ K, float* __restrict__ V)
{
    const float* B = (blockIdx.z == 0) ? Wq : (blockIdx.z == 1) ? Wk : Wv;
    float* C = (blockIdx.z == 0) ? Q : (blockIdx.z == 1) ? K : V;
    gemm64_body(A, B, nullptr, C, N_TOK, D_MODEL, D_MODEL,
                blockIdx.y * 64, blockIdx.x * 64);
}

// ---------------- class-compacted flash attention ----------------
// 128 threads = 32 query rows x 4 key-lanes. Each thread owns the FULL dot
// for its row (40 FMA QK + 40 FMA PV per key) -> 75% FMA instruction mix.
// sc[8] chunks (32 keys/chunk) keep regs ~110 -> 4 CTAs/SM.
// cp.async double-buffered K/V gather; final 2-step shuffle merge across lanes.
__global__ __launch_bounds__(128, 4) void attn_kernel(
    const float* __restrict__ Q, const float* __restrict__ Km,
    const float* __restrict__ Vm,
    const int* __restrict__ klist, const int* __restrict__ kcount,
    const int* __restrict__ qlist, const int* __restrict__ qcount,
    float* __restrict__ out)
{
    int grpIdx = blockIdx.x >> 7;
    int cls = (0x3105426 >> (grpIdx * 4)) & 7;   // heavy classes first
    int qt  = blockIdx.x & 127;
    int h   = blockIdx.y;
    int nQ = qcount[cls];
    if (qt * 32 >= nQ) return;
    int nK = kcount[cls];

    int tid = threadIdx.x;
    int grp = tid >> 2, lane4 = tid & 3;
    int qslot = qt * 32 + grp;
    bool valid = qslot < nQ;
    int row = valid ? qlist[cls * N_TOK + qslot] : qlist[cls * N_TOK];
    int hoff = h * DH;

    __shared__ float Ksm[2][64 * DH];
    __shared__ float Vsm[2][64 * DH];

    float q[DH];
    #pragma unroll
    for (int d4 = 0; d4 < 10; ++d4) {
        float4 t = *(const float4*)&Q[row * D_MODEL + hoff + d4 * 4];
        q[d4*4+0] = t.x; q[d4*4+1] = t.y; q[d4*4+2] = t.z; q[d4*4+3] = t.w;
    }

    float m = M_INIT, l = 0.f;
    float O[DH];
    #pragma unroll
    for (int d = 0; d < DH; ++d) O[d] = 0.f;

    const int* kl = klist + cls * N_TOK;
    int ntiles = (nK + 63) >> 6;

    // prefetch tile 0
    {
        int nloc = nK < 64 ? nK : 64;
        for (int v2 = tid; v2 < 640; v2 += 128) {
            int r = v2 / 10, d4 = v2 - r * 10;
            if (r < nloc) {
                int j = kl[r];
                cp_async16(&Ksm[0][r * DH + d4 * 4], Km + j * D_MODEL + hoff + d4 * 4);
                cp_async16(&Vsm[0][r * DH + d4 * 4], Vm + j * D_MODEL + hoff + d4 * 4);
            }
        }
        cp_commit();
    }

    for (int kt = 0; kt < ntiles; ++kt) {
        int buf = kt & 1;
        int base = kt << 6;
        int nloc = nK - base; if (nloc > 64) nloc = 64;

        if (kt + 1 < ntiles) {
            int base2 = base + 64;
            int nloc2 = nK - base2; if (nloc2 > 64) nloc2 = 64;
            float* Kb2 = Ksm[buf ^ 1];
            float* Vb2 = Vsm[buf ^ 1];
            for (int v2 = tid; v2 < 640; v2 += 128) {
                int r = v2 / 10, d4 = v2 - r * 10;
                if (r < nloc2) {
                    int j = kl[base2 + r];
                    cp_async16(&Kb2[r * DH + d4 * 4], Km + j * D_MODEL + hoff + d4 * 4);
                    cp_async16(&Vb2[r * DH + d4 * 4], Vm + j * D_MODEL + hoff + d4 * 4);
                }
            }
            cp_commit();
            cp_wait<1>();
        } else {
            cp_wait<0>();
        }
        __syncthreads();

        const float* Kb = Ksm[buf];
        const float* Vb = Vsm[buf];

        // 2 chunks of 32 keys (8 per lane)
        #pragma unroll 1
        for (int ch = 0; ch < 2; ++ch) {
            int j0 = ch << 5;
            float sc[8];
            #pragma unroll
            for (int s = 0; s < 8; ++s) {
                int jj = j0 | (s << 2) | lane4;   // interleaved: 4 distinct LDS addrs
                const float4* kp = (const float4*)(Kb + jj * DH);
                float d0 = 0.f, d1 = 0.f;
                #pragma unroll
                for (int d4 = 0; d4 < 10; d4 += 2) {
                    float4 k0 = kp[d4], k1 = kp[d4 + 1];
                    d0 = fmaf(q[d4*4+0], k0.x, d0); d0 = fmaf(q[d4*4+1], k0.y, d0);
                    d0 = fmaf(q[d4*4+2], k0.z, d0); d0 = fmaf(q[d4*4+3], k0.w, d0);
                    d1 = fmaf(q[d4*4+4], k1.x, d1); d1 = fmaf(q[d4*4+5], k1.y, d1);
                    d1 = fmaf(q[d4*4+6], k1.z, d1); d1 = fmaf(q[d4*4+7], k1.w, d1);
                }
                float v = (d0 + d1) * SCALE;
                sc[s] = (jj < nloc) ? v : NEG_BIG;
            }
            float tmax = sc[0];
            #pragma unroll
            for (int s = 1; s < 8; ++s) tmax = fmaxf(tmax, sc[s]);
            float mn = fmaxf(m, tmax);
            float f = __expf(m - mn);
            m = mn;
            l *= f;
            #pragma unroll
            for (int d = 0; d < DH; ++d) O[d] *= f;
            #pragma unroll
            for (int s = 0; s < 8; ++s) {
                int jj = j0 | (s << 2) | lane4;
                float p = __expf(sc[s] - m);   // 0 for invalid keys
                l += p;
                const float4* vp = (const float4*)(Vb + jj * DH);
                #pragma unroll
                for (int d4 = 0; d4 < 10; ++d4) {
                    float4 vv = vp[d4];
                    O[d4*4+0] = fmaf(p, vv.x, O[d4*4+0]);
                    O[d4*4+1] = fmaf(p, vv.y, O[d4*4+1]);
                    O[d4*4+2] = fmaf(p, vv.z, O[d4*4+2]);
                    O[d4*4+3] = fmaf(p, vv.w, O[d4*4+3]);
                }
            }
        }
        __syncthreads();
    }

    // merge (m,l,O) across the 4 lanes of each row group
    #pragma unroll
    for (int off = 1; off < 4; off <<= 1) {
        float mo = __shfl_xor_sync(0xffffffffu, m, off);
        float lo = __shfl_xor_sync(0xffffffffu, l, off);
        float mn = fmaxf(m, mo);
        float a = __expf(m - mn);
        float b = __expf(mo - mn);
        l = l * a + lo * b;
        #pragma unroll
        for (int d = 0; d < DH; ++d) {
            float od = __shfl_xor_sync(0xffffffffu, O[d], off);
            O[d] = O[d] * a + od * b;
        }
        m = mn;
    }

    if (valid) {
        float inv = 1.f / l;
        float* op = &out[row * D_MODEL + hoff + lane4 * 10];
        #pragma unroll
        for (int i = 0; i < 5; ++i) {
            float2 t; t.x = O[lane4*10 + 2*i] * inv; t.y = O[lane4*10 + 2*i + 1] * inv;
            *(float2*)(op + 2*i) = t;
        }
    }
}

extern "C" void kernel_launch(void* const* d_in, const int* in_sizes, int n_in,
                              void* d_out, int out_size) {
    const float* x     = (const float*)d_in[0];
    const float* gmask = (const float*)d_in[1];
    const float* Wq    = (const float*)d_in[2];
    const float* Wk    = (const float*)d_in[3];
    const float* Wv    = (const float*)d_in[4];
    const float* Wo    = (const float*)d_in[5];
    const float* bo    = (const float*)d_in[6];
    float* out = (float*)d_out;

    float *Qp, *Kp, *Vp, *Ap, *vmp, *pp; int *cp, *klp, *kcp, *qlp, *qcp;
    cudaGetSymbolAddress((void**)&Qp, g_Q);
    cudaGetSymbolAddress((void**)&Kp, g_K);
    cudaGetSymbolAddress((void**)&Vp, g_V);
    cudaGetSymbolAddress((void**)&Ap, g_A);
    cudaGetSymbolAddress((void**)&vmp, g_vmean);
    cudaGetSymbolAddress((void**)&pp, g_part);
    cudaGetSymbolAddress((void**)&cp, g_code);
    cudaGetSymbolAddress((void**)&klp, g_klist);
    cudaGetSymbolAddress((void**)&kcp, g_kcount);
    cudaGetSymbolAddress((void**)&qlp, g_qlist);
    cudaGetSymbolAddress((void**)&qcp, g_qcount);

    code_kernel<<<16, 256>>>(gmask, cp);
    build_lists<<<7, 256>>>(cp, klp, kcp, qlp, qcp);
    gemm64_qkv<<<dim3(D_MODEL / 64, N_TOK / 64, 3), 256>>>(x, Wq, Wk, Wv, Qp, Kp, Vp);
    attn_kernel<<<dim3(7 * 128, HEADS), 128>>>(Qp, Kp, Vp, klp, kcp, qlp, qcp, Ap);
    vmean1<<<32, 320>>>(Vp, pp);
    vmean2<<<1, 320>>>(pp, vmp);
    fill_inactive<<<N_TOK, 64>>>(cp, vmp, Ap);
    gemm64<<<dim3(D_MODEL / 64, N_TOK / 64), 256>>>(Ap, Wo, bo, out, N_TOK, D_MODEL, D_MODEL);
}

// round 9
// speedup vs baseline: 1.4565x; 1.0041x over previous
#include <cuda_runtime.h>
#include <cuda_fp16.h>
#include <math.h>

#define N_TOK 4096
#define D_MODEL 320
#define HEADS 8
#define DH 40
#define SCALE 0.15811388300841897f  // 40^-0.5
#define NEG_BIG  (-3.0e38f)
#define M_INIT   (-1.0e37f)

// ---------------- scratch (no allocs allowed) ----------------
__device__ float  g_Q[N_TOK * D_MODEL];
__device__ __half g_Kh[N_TOK * D_MODEL];   // K only used by attention -> fp16
__device__ float  g_V[N_TOK * D_MODEL];
__device__ float  g_A[N_TOK * D_MODEL];
__device__ int    g_code[N_TOK];
__device__ float  g_vmean[D_MODEL];
__device__ float  g_part[32 * D_MODEL];
__device__ int    g_klist[7 * N_TOK];
__device__ int    g_kcount[7];
__device__ int    g_qlist[7 * N_TOK];
__device__ int    g_qcount[7];

// ---------------- cp.async helpers ----------------
__device__ __forceinline__ void cp_async16(void* smem, const void* gmem) {
    unsigned sa = (unsigned)__cvta_generic_to_shared(smem);
    asm volatile("cp.async.cg.shared.global [%0], [%1], 16;" :: "r"(sa), "l"(gmem));
}
__device__ __forceinline__ void cp_commit() {
    asm volatile("cp.async.commit_group;");
}
template<int N> __device__ __forceinline__ void cp_wait() {
    asm volatile("cp.async.wait_group %0;" :: "n"(N));
}

// ---------------- phase-code kernel ----------------
__global__ void code_kernel(const float* __restrict__ g, int* __restrict__ code) {
    int i = blockIdx.x * 256 + threadIdx.x;
    if (i < N_TOK) {
        int c = 0;
        if (g[i]           > 0.5f) c |= 1;
        if (g[N_TOK + i]   > 0.5f) c |= 2;
        if (g[2*N_TOK + i] > 0.5f) c |= 4;
        code[i] = c;
    }
}

// ---------------- deterministic per-class list compaction (ballot scan) ----------------
__global__ __launch_bounds__(256) void build_lists(
    const int* __restrict__ code,
    int* __restrict__ klist, int* __restrict__ kcount,
    int* __restrict__ qlist, int* __restrict__ qcount)
{
    int c = blockIdx.x + 1;
    int tid = threadIdx.x;
    int lane = tid & 31, wid = tid >> 5;
    __shared__ int wk[8], wq[8];
    __shared__ int kbase, qbase;
    if (tid == 0) { kbase = 0; qbase = 0; }
    __syncthreads();

    int loff = (c - 1) * N_TOK;
    for (int t0 = 0; t0 < N_TOK; t0 += 256) {
        int i = t0 + tid;
        int ci = code[i];
        int kp = (ci & c) ? 1 : 0;
        int qp = (ci == c) ? 1 : 0;

        unsigned kb = __ballot_sync(0xffffffffu, kp);
        unsigned qb = __ballot_sync(0xffffffffu, qp);
        int kpre = __popc(kb & ((1u << lane) - 1));
        int qpre = __popc(qb & ((1u << lane) - 1));
        if (lane == 0) { wk[wid] = __popc(kb); wq[wid] = __popc(qb); }
        __syncthreads();
        if (tid == 0) {
            int rk = kbase, rq = qbase;
            #pragma unroll
            for (int w = 0; w < 8; ++w) {
                int tk = wk[w]; wk[w] = rk; rk += tk;
                int tq = wq[w]; wq[w] = rq; rq += tq;
            }
            kbase = rk; qbase = rq;
        }
        __syncthreads();
        if (kp) klist[loff + wk[wid] + kpre] = i;
        if (qp) qlist[loff + wq[wid] + qpre] = i;
        __syncthreads();
    }
    if (tid == 0) { kcount[c - 1] = kbase; qcount[c - 1] = qbase; }
}

// ---------------- coalesced 2-stage column mean of V ----------------
__global__ void vmean1(const float* __restrict__ V, float* __restrict__ part) {
    int b = blockIdx.x;
    int c = threadIdx.x;
    float s = 0.f;
    int r0 = b * 128;
    #pragma unroll 4
    for (int r = 0; r < 128; ++r) s += V[(r0 + r) * D_MODEL + c];
    part[b * D_MODEL + c] = s;
}
__global__ void vmean2(const float* __restrict__ part, float* __restrict__ vm) {
    int c = threadIdx.x;
    float s = 0.f;
    #pragma unroll
    for (int b = 0; b < 32; ++b) s += part[b * D_MODEL + c];
    vm[c] = s * (1.f / (float)N_TOK);
}

// ---------------- fully-masked rows -> vmean ----------------
__global__ void fill_inactive(const int* __restrict__ code,
                              const float* __restrict__ vmean,
                              float* __restrict__ A) {
    int row = blockIdx.x;
    if (code[row] != 0) return;
    for (int d = threadIdx.x; d < D_MODEL; d += 64)
        A[row * D_MODEL + d] = vmean[d];
}

// ---------------- tiled fp32 GEMM body (optional fp16 output) ----------------
template<bool HALF_OUT>
__device__ __forceinline__ void gemm64_body(
    const float* __restrict__ A, const float* __restrict__ B,
    const float* __restrict__ bias, void* __restrict__ C,
    int M, int N, int K, int m0, int n0)
{
    __shared__ float As[16][68];
    __shared__ float Bs[16][68];
    int tid = threadIdx.x;
    int ty = tid >> 4, tx = tid & 15;

    int lr = tid >> 2;
    int lk = (tid & 3) * 4;
    int bk = tid >> 4;
    int bc = (tid & 15) * 4;

    float acc[4][4];
    #pragma unroll
    for (int i = 0; i < 4; ++i)
        #pragma unroll
        for (int j = 0; j < 4; ++j) acc[i][j] = 0.f;

    for (int k0 = 0; k0 < K; k0 += 16) {
        float4 av = *(const float4*)&A[(m0 + lr) * K + k0 + lk];
        As[lk + 0][lr] = av.x; As[lk + 1][lr] = av.y;
        As[lk + 2][lr] = av.z; As[lk + 3][lr] = av.w;
        float4 bv = *(const float4*)&B[(k0 + bk) * N + n0 + bc];
        *(float4*)&Bs[bk][bc] = bv;
        __syncthreads();
        #pragma unroll
        for (int kk = 0; kk < 16; ++kk) {
            float a[4], b[4];
            #pragma unroll
            for (int i = 0; i < 4; ++i) a[i] = As[kk][ty * 4 + i];
            #pragma unroll
            for (int j = 0; j < 4; ++j) b[j] = Bs[kk][tx * 4 + j];
            #pragma unroll
            for (int i = 0; i < 4; ++i)
                #pragma unroll
                for (int j = 0; j < 4; ++j)
                    acc[i][j] = fmaf(a[i], b[j], acc[i][j]);
        }
        __syncthreads();
    }
    #pragma unroll
    for (int i = 0; i < 4; ++i) {
        int row = m0 + ty * 4 + i;
        #pragma unroll
        for (int j = 0; j < 4; ++j) {
            int col = n0 + tx * 4 + j;
            float v = acc[i][j];
            if (bias) v += bias[col];
            if (HALF_OUT) ((__half*)C)[row * N + col] = __float2half(v);
            else          ((float*)C)[row * N + col] = v;
        }
    }
}

__global__ __launch_bounds__(256) void gemm64(
    const float* __restrict__ A, const float* __restrict__ B,
    const float* __restrict__ bias, float* __restrict__ C,
    int M, int N, int K)
{
    gemm64_body<false>(A, B, bias, C, M, N, K, blockIdx.y * 64, blockIdx.x * 64);
}

__global__ __launch_bounds__(256) void gemm64_qkv(
    const float* __restrict__ A,
    const float* __restrict__ Wq, const float* __restrict__ Wk,
    const float* __restrict__ Wv,
    float* __restrict__ Q, __half* __restrict__ Kh, float* __restrict__ V)
{
    int m0 = blockIdx.y * 64, n0 = blockIdx.x * 64;
    if (blockIdx.z == 0)
        gemm64_body<false>(A, Wq, nullptr, Q, N_TOK, D_MODEL, D_MODEL, m0, n0);
    else if (blockIdx.z == 1)
        gemm64_body<true>(A, Wk, nullptr, Kh, N_TOK, D_MODEL, D_MODEL, m0, n0);
    else
        gemm64_body<false>(A, Wv, nullptr, V, N_TOK, D_MODEL, D_MODEL, m0, n0);
}

// ---------------- class-compacted flash attention (fp16 K, fp32 V) ----------------
// 128 threads = 32 query rows x 4 key-lanes. Score dot: 5 LDS.128 + 20 HFMA2
// per key per thread (fp16 K, fp16 q regs). V accumulate stays fp32.
// sc[4] chunks (16 keys) keep regs ~100 -> 5 CTAs/SM.
__global__ __launch_bounds__(128, 5) void attn_kernel(
    const float* __restrict__ Q, const __half* __restrict__ Kh,
    const float* __restrict__ Vm,
    const int* __restrict__ klist, const int* __restrict__ kcount,
    const int* __restrict__ qlist, const int* __restrict__ qcount,
    float* __restrict__ out)
{
    int grpIdx = blockIdx.x >> 7;
    int cls = (0x3105426 >> (grpIdx * 4)) & 7;   // heavy classes first
    int qt  = blockIdx.x & 127;
    int h   = blockIdx.y;
    int nQ = qcount[cls];
    if (qt * 32 >= nQ) return;
    int nK = kcount[cls];

    int tid = threadIdx.x;
    int grp = tid >> 2, lane4 = tid & 3;
    int qslot = qt * 32 + grp;
    bool valid = qslot < nQ;
    int row = valid ? qlist[cls * N_TOK + qslot] : qlist[cls * N_TOK];
    int hoff = h * DH;

    __shared__ __half Ksm[2][64 * DH];   // 10,240 B
    __shared__ float  Vsm[2][64 * DH];   // 20,480 B

    // q as 20 half2 regs
    __half2 q2[20];
    #pragma unroll
    for (int d4 = 0; d4 < 10; ++d4) {
        float4 t = *(const float4*)&Q[row * D_MODEL + hoff + d4 * 4];
        q2[d4*2+0] = __floats2half2_rn(t.x, t.y);
        q2[d4*2+1] = __floats2half2_rn(t.z, t.w);
    }

    float m = M_INIT, l = 0.f;
    float O[DH];
    #pragma unroll
    for (int d = 0; d < DH; ++d) O[d] = 0.f;

    const int* kl = klist + cls * N_TOK;
    int ntiles = (nK + 63) >> 6;

    // prefetch tile 0:  K rows = 5 x 16B chunks, V rows = 10 x 16B chunks
    {
        int nloc = nK < 64 ? nK : 64;
        for (int v2 = tid; v2 < 320; v2 += 128) {
            int r = v2 / 5, c = v2 - r * 5;
            if (r < nloc) {
                int j = kl[r];
                cp_async16(&Ksm[0][r * DH + c * 8], Kh + j * D_MODEL + hoff + c * 8);
            }
        }
        for (int v2 = tid; v2 < 640; v2 += 128) {
            int r = v2 / 10, c = v2 - r * 10;
            if (r < nloc) {
                int j = kl[r];
                cp_async16(&Vsm[0][r * DH + c * 4], Vm + j * D_MODEL + hoff + c * 4);
            }
        }
        cp_commit();
    }

    for (int kt = 0; kt < ntiles; ++kt) {
        int buf = kt & 1;
        int base = kt << 6;
        int nloc = nK - base; if (nloc > 64) nloc = 64;

        if (kt + 1 < ntiles) {
            int base2 = base + 64;
            int nloc2 = nK - base2; if (nloc2 > 64) nloc2 = 64;
            __half* Kb2 = Ksm[buf ^ 1];
            float*  Vb2 = Vsm[buf ^ 1];
            for (int v2 = tid; v2 < 320; v2 += 128) {
                int r = v2 / 5, c = v2 - r * 5;
                if (r < nloc2) {
                    int j = kl[base2 + r];
                    cp_async16(&Kb2[r * DH + c * 8], Kh + j * D_MODEL + hoff + c * 8);
                }
            }
            for (int v2 = tid; v2 < 640; v2 += 128) {
                int r = v2 / 10, c = v2 - r * 10;
                if (r < nloc2) {
                    int j = kl[base2 + r];
                    cp_async16(&Vb2[r * DH + c * 4], Vm + j * D_MODEL + hoff + c * 4);
                }
            }
            cp_commit();
            cp_wait<1>();
        } else {
            cp_wait<0>();
        }
        __syncthreads();

        const __half* Kb = Ksm[buf];
        const float*  Vb = Vsm[buf];

        // 4 chunks of 16 keys (4 per lane)
        #pragma unroll 1
        for (int ch = 0; ch < 4; ++ch) {
            int j0 = ch << 4;
            float sc[4];
            #pragma unroll
            for (int s = 0; s < 4; ++s) {
                int jj = j0 | (s << 2) | lane4;   // interleaved lanes
                const float4* kp = (const float4*)(Kb + jj * DH);
                __half2 a0 = __float2half2_rn(0.f), a1 = a0, a2 = a0, a3 = a0;
                #pragma unroll
                for (int c = 0; c < 5; ++c) {
                    float4 kv = kp[c];   // 8 halves
                    a0 = __hfma2(q2[c*4+0], *(const __half2*)&kv.x, a0);
                    a1 = __hfma2(q2[c*4+1], *(const __half2*)&kv.y, a1);
                    a2 = __hfma2(q2[c*4+2], *(const __half2*)&kv.z, a2);
                    a3 = __hfma2(q2[c*4+3], *(const __half2*)&kv.w, a3);
                }
                __half2 ss = __hadd2(__hadd2(a0, a1), __hadd2(a2, a3));
                float2 f = __half22float2(ss);
                float v = (f.x + f.y) * SCALE;
                sc[s] = (jj < nloc) ? v : NEG_BIG;
            }
            float tmax = fmaxf(fmaxf(sc[0], sc[1]), fmaxf(sc[2], sc[3]));
            float mn = fmaxf(m, tmax);
            float f = __expf(m - mn);
            m = mn;
            l *= f;
            #pragma unroll
            for (int d = 0; d < DH; ++d) O[d] *= f;
            #pragma unroll
            for (int s = 0; s < 4; ++s) {
                int jj = j0 | (s << 2) | lane4;
                float p = __expf(sc[s] - m);   // 0 for invalid keys
                l += p;
                const float4* vp = (const float4*)(Vb + jj * DH);
                #pragma unroll
                for (int d4 = 0; d4 < 10; ++d4) {
                    float4 vv = vp[d4];
                    O[d4*4+0] = fmaf(p, vv.x, O[d4*4+0]);
                    O[d4*4+1] = fmaf(p, vv.y, O[d4*4+1]);
                    O[d4*4+2] = fmaf(p, vv.z, O[d4*4+2]);
                    O[d4*4+3] = fmaf(p, vv.w, O[d4*4+3]);
                }
            }
        }
        __syncthreads();
    }

    // merge (m,l,O) across the 4 lanes of each row group
    #pragma unroll
    for (int off = 1; off < 4; off <<= 1) {
        float mo = __shfl_xor_sync(0xffffffffu, m, off);
        float lo = __shfl_xor_sync(0xffffffffu, l, off);
        float mn = fmaxf(m, mo);
        float a = __expf(m - mn);
        float b = __expf(mo - mn);
        l = l * a + lo * b;
        #pragma unroll
        for (int d = 0; d < DH; ++d) {
            float od = __shfl_xor_sync(0xffffffffu, O[d], off);
            O[d] = O[d] * a + od * b;
        }
        m = mn;
    }

    if (valid) {
        float inv = 1.f / l;
        float* op = &out[row * D_MODEL + hoff + lane4 * 10];
        #pragma unroll
        for (int i = 0; i < 5; ++i) {
            float2 t; t.x = O[lane4*10 + 2*i] * inv; t.y = O[lane4*10 + 2*i + 1] * inv;
            *(float2*)(op + 2*i) = t;
        }
    }
}

extern "C" void kernel_launch(void* const* d_in, const int* in_sizes, int n_in,
                              void* d_out, int out_size) {
    const float* x     = (const float*)d_in[0];
    const float* gmask = (const float*)d_in[1];
    const float* Wq    = (const float*)d_in[2];
    const float* Wk    = (const float*)d_in[3];
    const float* Wv    = (const float*)d_in[4];
    const float* Wo    = (const float*)d_in[5];
    const float* bo    = (const float*)d_in[6];
    float* out = (float*)d_out;

    float *Qp, *Vp, *Ap, *vmp, *pp; __half* Khp;
    int *cp, *klp, *kcp, *qlp, *qcp;
    cudaGetSymbolAddress((void**)&Qp, g_Q);
    cudaGetSymbolAddress((void**)&Khp, g_Kh);
    cudaGetSymbolAddress((void**)&Vp, g_V);
    cudaGetSymbolAddress((void**)&Ap, g_A);
    cudaGetSymbolAddress((void**)&vmp, g_vmean);
    cudaGetSymbolAddress((void**)&pp, g_part);
    cudaGetSymbolAddress((void**)&cp, g_code);
    cudaGetSymbolAddress((void**)&klp, g_klist);
    cudaGetSymbolAddress((void**)&kcp, g_kcount);
    cudaGetSymbolAddress((void**)&qlp, g_qlist);
    cudaGetSymbolAddress((void**)&qcp, g_qcount);

    code_kernel<<<16, 256>>>(gmask, cp);
    build_lists<<<7, 256>>>(cp, klp, kcp, qlp, qcp);
    gemm64_qkv<<<dim3(D_MODEL / 64, N_TOK / 64, 3), 256>>>(x, Wq, Wk, Wv, Qp, Khp, Vp);
    attn_kernel<<<dim3(7 * 128, HEADS), 128>>>(Qp, Khp, Vp, klp, kcp, qlp, qcp, Ap);
    vmean1<<<32, 320>>>(Vp, pp);
    vmean2<<<1, 320>>>(pp, vmp);
    fill_inactive<<<N_TOK, 64>>>(cp, vmp, Ap);
    gemm64<<<dim3(D_MODEL / 64, N_TOK / 64), 256>>>(Ap, Wo, bo, out, N_TOK, D_MODEL, D_MODEL);
}

// round 11
// speedup vs baseline: 1.5328x; 1.0524x over previous
#include <cuda_runtime.h>
#include <cuda_fp16.h>
#include <math.h>

#define N_TOK 4096
#define D_MODEL 320
#define HEADS 8
#define DH 40
#define SCALE 0.15811388300841897f  // 40^-0.5
#define NEG_BIG  (-3.0e38f)
#define M_INIT   (-1.0e37f)

// ---------------- scratch (no allocs allowed) ----------------
__device__ float  g_Q[N_TOK * D_MODEL];
__device__ __half g_Kh[N_TOK * D_MODEL];   // K only used by attention -> fp16
__device__ float  g_V[N_TOK * D_MODEL];
__device__ float  g_A[N_TOK * D_MODEL];
__device__ int    g_code[N_TOK];
__device__ float  g_vmean[D_MODEL];
__device__ float  g_part[32 * D_MODEL];
__device__ int    g_klist[7 * N_TOK];
__device__ int    g_kcount[7];
__device__ int    g_qlist[7 * N_TOK];
__device__ int    g_qcount[7];

// ---------------- cp.async helpers ----------------
__device__ __forceinline__ void cp_async16(void* smem, const void* gmem) {
    unsigned sa = (unsigned)__cvta_generic_to_shared(smem);
    asm volatile("cp.async.cg.shared.global [%0], [%1], 16;" :: "r"(sa), "l"(gmem));
}
__device__ __forceinline__ void cp_commit() {
    asm volatile("cp.async.commit_group;");
}
template<int N> __device__ __forceinline__ void cp_wait() {
    asm volatile("cp.async.wait_group %0;" :: "n"(N));
}

// ---------------- phase-code kernel ----------------
__global__ void code_kernel(const float* __restrict__ g, int* __restrict__ code) {
    int i = blockIdx.x * 256 + threadIdx.x;
    if (i < N_TOK) {
        int c = 0;
        if (g[i]           > 0.5f) c |= 1;
        if (g[N_TOK + i]   > 0.5f) c |= 2;
        if (g[2*N_TOK + i] > 0.5f) c |= 4;
        code[i] = c;
    }
}

// ---------------- deterministic per-class list compaction (ballot scan) ----------------
__global__ __launch_bounds__(256) void build_lists(
    const int* __restrict__ code,
    int* __restrict__ klist, int* __restrict__ kcount,
    int* __restrict__ qlist, int* __restrict__ qcount)
{
    int c = blockIdx.x + 1;
    int tid = threadIdx.x;
    int lane = tid & 31, wid = tid >> 5;
    __shared__ int wk[8], wq[8];
    __shared__ int kbase, qbase;
    if (tid == 0) { kbase = 0; qbase = 0; }
    __syncthreads();

    int loff = (c - 1) * N_TOK;
    for (int t0 = 0; t0 < N_TOK; t0 += 256) {
        int i = t0 + tid;
        int ci = code[i];
        int kp = (ci & c) ? 1 : 0;
        int qp = (ci == c) ? 1 : 0;

        unsigned kb = __ballot_sync(0xffffffffu, kp);
        unsigned qb = __ballot_sync(0xffffffffu, qp);
        int kpre = __popc(kb & ((1u << lane) - 1));
        int qpre = __popc(qb & ((1u << lane) - 1));
        if (lane == 0) { wk[wid] = __popc(kb); wq[wid] = __popc(qb); }
        __syncthreads();
        if (tid == 0) {
            int rk = kbase, rq = qbase;
            #pragma unroll
            for (int w = 0; w < 8; ++w) {
                int tk = wk[w]; wk[w] = rk; rk += tk;
                int tq = wq[w]; wq[w] = rq; rq += tq;
            }
            kbase = rk; qbase = rq;
        }
        __syncthreads();
        if (kp) klist[loff + wk[wid] + kpre] = i;
        if (qp) qlist[loff + wq[wid] + qpre] = i;
        __syncthreads();
    }
    if (tid == 0) { kcount[c - 1] = kbase; qcount[c - 1] = qbase; }
}

// ---------------- coalesced 2-stage column mean of V ----------------
__global__ void vmean1(const float* __restrict__ V, float* __restrict__ part) {
    int b = blockIdx.x;
    int c = threadIdx.x;
    float s = 0.f;
    int r0 = b * 128;
    #pragma unroll 4
    for (int r = 0; r < 128; ++r) s += V[(r0 + r) * D_MODEL + c];
    part[b * D_MODEL + c] = s;
}
__global__ void vmean2(const float* __restrict__ part, float* __restrict__ vm) {
    int c = threadIdx.x;
    float s = 0.f;
    #pragma unroll
    for (int b = 0; b < 32; ++b) s += part[b * D_MODEL + c];
    vm[c] = s * (1.f / (float)N_TOK);
}

// ---------------- fully-masked rows -> vmean ----------------
__global__ void fill_inactive(const int* __restrict__ code,
                              const float* __restrict__ vmean,
                              float* __restrict__ A) {
    int row = blockIdx.x;
    if (code[row] != 0) return;
    for (int d = threadIdx.x; d < D_MODEL; d += 64)
        A[row * D_MODEL + d] = vmean[d];
}

// ---------------- tiled fp32 GEMM body (optional fp16 output) ----------------
template<bool HALF_OUT>
__device__ __forceinline__ void gemm64_body(
    const float* __restrict__ A, const float* __restrict__ B,
    const float* __restrict__ bias, void* __restrict__ C,
    int M, int N, int K, int m0, int n0)
{
    __shared__ float As[16][68];
    __shared__ float Bs[16][68];
    int tid = threadIdx.x;
    int ty = tid >> 4, tx = tid & 15;

    int lr = tid >> 2;
    int lk = (tid & 3) * 4;
    int bk = tid >> 4;
    int bc = (tid & 15) * 4;

    float acc[4][4];
    #pragma unroll
    for (int i = 0; i < 4; ++i)
        #pragma unroll
        for (int j = 0; j < 4; ++j) acc[i][j] = 0.f;

    for (int k0 = 0; k0 < K; k0 += 16) {
        float4 av = *(const float4*)&A[(m0 + lr) * K + k0 + lk];
        As[lk + 0][lr] = av.x; As[lk + 1][lr] = av.y;
        As[lk + 2][lr] = av.z; As[lk + 3][lr] = av.w;
        float4 bv = *(const float4*)&B[(k0 + bk) * N + n0 + bc];
        *(float4*)&Bs[bk][bc] = bv;
        __syncthreads();
        #pragma unroll
        for (int kk = 0; kk < 16; ++kk) {
            float a[4], b[4];
            #pragma unroll
            for (int i = 0; i < 4; ++i) a[i] = As[kk][ty * 4 + i];
            #pragma unroll
            for (int j = 0; j < 4; ++j) b[j] = Bs[kk][tx * 4 + j];
            #pragma unroll
            for (int i = 0; i < 4; ++i)
                #pragma unroll
                for (int j = 0; j < 4; ++j)
                    acc[i][j] = fmaf(a[i], b[j], acc[i][j]);
        }
        __syncthreads();
    }
    #pragma unroll
    for (int i = 0; i < 4; ++i) {
        int row = m0 + ty * 4 + i;
        #pragma unroll
        for (int j = 0; j < 4; ++j) {
            int col = n0 + tx * 4 + j;
            float v = acc[i][j];
            if (bias) v += bias[col];
            if (HALF_OUT) ((__half*)C)[row * N + col] = __float2half(v);
            else          ((float*)C)[row * N + col] = v;
        }
    }
}

__global__ __launch_bounds__(256) void gemm64(
    const float* __restrict__ A, const float* __restrict__ B,
    const float* __restrict__ bias, float* __restrict__ C,
    int M, int N, int K)
{
    gemm64_body<false>(A, B, bias, C, M, N, K, blockIdx.y * 64, blockIdx.x * 64);
}

__global__ __launch_bounds__(256) void gemm64_qkv(
    const float* __restrict__ A,
    const float* __restrict__ Wq, const float* __restrict__ Wk,
    const float* __restrict__ Wv,
    float* __restrict__ Q, __half* __restrict__ Kh, float* __restrict__ V)
{
    int m0 = blockIdx.y * 64, n0 = blockIdx.x * 64;
    if (blockIdx.z == 0)
        gemm64_body<false>(A, Wq, nullptr, Q, N_TOK, D_MODEL, D_MODEL, m0, n0);
    else if (blockIdx.z == 1)
        gemm64_body<true>(A, Wk, nullptr, Kh, N_TOK, D_MODEL, D_MODEL, m0, n0);
    else
        gemm64_body<false>(A, Wv, nullptr, V, N_TOK, D_MODEL, D_MODEL, m0, n0);
}

// ---------------- class-compacted flash attention (fp16 K, fp32 V, 2 rows/thread) ----------------
// 128 threads = 32 groups x 4 key-lanes; each thread owns TWO query rows.
// Every K-row smem load produces 2 scores; every V-row load feeds 2 accumulators.
// -> LDS per (row,key) pair halved vs R9, ILP doubled.
__global__ __launch_bounds__(128, 3) void attn_kernel(
    const float* __restrict__ Q, const __half* __restrict__ Kh,
    const float* __restrict__ Vm,
    const int* __restrict__ klist, const int* __restrict__ kcount,
    const int* __restrict__ qlist, const int* __restrict__ qcount,
    float* __restrict__ out)
{
    int grpIdx = blockIdx.x >> 4;                 // 16 qtiles per class
    int cls = (0x3105426 >> (grpIdx * 4)) & 7;    // heavy classes first
    int qt  = blockIdx.x & 15;
    int h   = blockIdx.y;
    int nQ = qcount[cls];
    if (qt * 64 >= nQ) return;
    int nK = kcount[cls];

    int tid = threadIdx.x;
    int grp = tid >> 2, lane4 = tid & 3;
    int qslot0 = qt * 64 + grp;
    int qslot1 = qslot0 + 32;
    bool valid0 = qslot0 < nQ;
    bool valid1 = qslot1 < nQ;
    int row0 = valid0 ? qlist[cls * N_TOK + qslot0] : qlist[cls * N_TOK];
    int row1 = valid1 ? qlist[cls * N_TOK + qslot1] : qlist[cls * N_TOK];
    int hoff = h * DH;

    __shared__ __half Ksm[2][64 * DH];   // 10,240 B
    __shared__ float  Vsm[2][64 * DH];   // 20,480 B

    // two q rows as half2 regs
    __half2 qa[20], qb[20];
    #pragma unroll
    for (int d4 = 0; d4 < 10; ++d4) {
        float4 t = *(const float4*)&Q[row0 * D_MODEL + hoff + d4 * 4];
        qa[d4*2+0] = __floats2half2_rn(t.x, t.y);
        qa[d4*2+1] = __floats2half2_rn(t.z, t.w);
        float4 u = *(const float4*)&Q[row1 * D_MODEL + hoff + d4 * 4];
        qb[d4*2+0] = __floats2half2_rn(u.x, u.y);
        qb[d4*2+1] = __floats2half2_rn(u.z, u.w);
    }

    float ma = M_INIT, la = 0.f, mb = M_INIT, lb = 0.f;
    float Oa[DH], Ob[DH];
    #pragma unroll
    for (int d = 0; d < DH; ++d) { Oa[d] = 0.f; Ob[d] = 0.f; }

    const int* kl = klist + cls * N_TOK;
    int ntiles = (nK + 63) >> 6;

    // prefetch tile 0
    {
        int nloc = nK < 64 ? nK : 64;
        for (int v2 = tid; v2 < 320; v2 += 128) {
            int r = v2 / 5, c = v2 - r * 5;
            if (r < nloc) {
                int j = kl[r];
                cp_async16(&Ksm[0][r * DH + c * 8], Kh + j * D_MODEL + hoff + c * 8);
            }
        }
        for (int v2 = tid; v2 < 640; v2 += 128) {
            int r = v2 / 10, c = v2 - r * 10;
            if (r < nloc) {
                int j = kl[r];
                cp_async16(&Vsm[0][r * DH + c * 4], Vm + j * D_MODEL + hoff + c * 4);
            }
        }
        cp_commit();
    }

    for (int kt = 0; kt < ntiles; ++kt) {
        int buf = kt & 1;
        int base = kt << 6;
        int nloc = nK - base; if (nloc > 64) nloc = 64;

        if (kt + 1 < ntiles) {
            int base2 = base + 64;
            int nloc2 = nK - base2; if (nloc2 > 64) nloc2 = 64;
            __half* Kb2 = Ksm[buf ^ 1];
            float*  Vb2 = Vsm[buf ^ 1];
            for (int v2 = tid; v2 < 320; v2 += 128) {
                int r = v2 / 5, c = v2 - r * 5;
                if (r < nloc2) {
                    int j = kl[base2 + r];
                    cp_async16(&Kb2[r * DH + c * 8], Kh + j * D_MODEL + hoff + c * 8);
                }
            }
            for (int v2 = tid; v2 < 640; v2 += 128) {
                int r = v2 / 10, c = v2 - r * 10;
                if (r < nloc2) {
                    int j = kl[base2 + r];
                    cp_async16(&Vb2[r * DH + c * 4], Vm + j * D_MODEL + hoff + c * 4);
                }
            }
            cp_commit();
            cp_wait<1>();
        } else {
            cp_wait<0>();
        }
        __syncthreads();

        const __half* Kb = Ksm[buf];
        const float*  Vb = Vsm[buf];

        // 4 chunks of 16 keys (4 per lane)
        #pragma unroll 1
        for (int ch = 0; ch < 4; ++ch) {
            int j0 = ch << 4;
            float sa[4], sb[4];
            #pragma unroll
            for (int s = 0; s < 4; ++s) {
                int jj = j0 | (s << 2) | lane4;
                const float4* kp = (const float4*)(Kb + jj * DH);
                __half2 a0 = __float2half2_rn(0.f), a1 = a0, a2 = a0, a3 = a0;
                __half2 b0 = a0, b1 = a0, b2 = a0, b3 = a0;
                #pragma unroll
                for (int c = 0; c < 5; ++c) {
                    float4 kv = kp[c];   // 8 halves, reused for both rows
                    __half2 k0 = *(const __half2*)&kv.x;
                    __half2 k1 = *(const __half2*)&kv.y;
                    __half2 k2 = *(const __half2*)&kv.z;
                    __half2 k3 = *(const __half2*)&kv.w;
                    a0 = __hfma2(qa[c*4+0], k0, a0);  b0 = __hfma2(qb[c*4+0], k0, b0);
                    a1 = __hfma2(qa[c*4+1], k1, a1);  b1 = __hfma2(qb[c*4+1], k1, b1);
                    a2 = __hfma2(qa[c*4+2], k2, a2);  b2 = __hfma2(qb[c*4+2], k2, b2);
                    a3 = __hfma2(qa[c*4+3], k3, a3);  b3 = __hfma2(qb[c*4+3], k3, b3);
                }
                __half2 ssa = __hadd2(__hadd2(a0, a1), __hadd2(a2, a3));
                __half2 ssb = __hadd2(__hadd2(b0, b1), __hadd2(b2, b3));
                float2 fa = __half22float2(ssa);
                float2 fb = __half22float2(ssb);
                bool ok = jj < nloc;
                sa[s] = ok ? (fa.x + fa.y) * SCALE : NEG_BIG;
                sb[s] = ok ? (fb.x + fb.y) * SCALE : NEG_BIG;
            }
            float tma = fmaxf(fmaxf(sa[0], sa[1]), fmaxf(sa[2], sa[3]));
            float tmb = fmaxf(fmaxf(sb[0], sb[1]), fmaxf(sb[2], sb[3]));
            float mna = fmaxf(ma, tma);
            float mnb = fmaxf(mb, tmb);
            float fa = __expf(ma - mna);
            float fb = __expf(mb - mnb);
            ma = mna; mb = mnb;
            la *= fa; lb *= fb;
            #pragma unroll
            for (int d = 0; d < DH; ++d) { Oa[d] *= fa; Ob[d] *= fb; }
            #pragma unroll
            for (int s = 0; s < 4; ++s) {
                int jj = j0 | (s << 2) | lane4;
                float pa = __expf(sa[s] - ma);
                float pb = __expf(sb[s] - mb);
                la += pa; lb += pb;
                const float4* vp = (const float4*)(Vb + jj * DH);
                #pragma unroll
                for (int d4 = 0; d4 < 10; ++d4) {
                    float4 vv = vp[d4];   // reused for both rows
                    Oa[d4*4+0] = fmaf(pa, vv.x, Oa[d4*4+0]);
                    Ob[d4*4+0] = fmaf(pb, vv.x, Ob[d4*4+0]);
                    Oa[d4*4+1] = fmaf(pa, vv.y, Oa[d4*4+1]);
                    Ob[d4*4+1] = fmaf(pb, vv.y, Ob[d4*4+1]);
                    Oa[d4*4+2] = fmaf(pa, vv.z, Oa[d4*4+2]);
                    Ob[d4*4+2] = fmaf(pb, vv.z, Ob[d4*4+2]);
                    Oa[d4*4+3] = fmaf(pa, vv.w, Oa[d4*4+3]);
                    Ob[d4*4+3] = fmaf(pb, vv.w, Ob[d4*4+3]);
                }
            }
        }
        __syncthreads();
    }

    // merge (m,l,O) across the 4 lanes of each group, both rows
    #pragma unroll
    for (int off = 1; off < 4; off <<= 1) {
        float moa = __shfl_xor_sync(0xffffffffu, ma, off);
        float loa = __shfl_xor_sync(0xffffffffu, la, off);
        float mob = __shfl_xor_sync(0xffffffffu, mb, off);
        float lob = __shfl_xor_sync(0xffffffffu, lb, off);
        float mna = fmaxf(ma, moa);
        float mnb = fmaxf(mb, mob);
        float aa = __expf(ma - mna), ba = __expf(moa - mna);
        float ab = __expf(mb - mnb), bb = __expf(mob - mnb);
        la = la * aa + loa * ba;
        lb = lb * ab + lob * bb;
        #pragma unroll
        for (int d = 0; d < DH; ++d) {
            float oda = __shfl_xor_sync(0xffffffffu, Oa[d], off);
            float odb = __shfl_xor_sync(0xffffffffu, Ob[d], off);
            Oa[d] = Oa[d] * aa + oda * ba;
            Ob[d] = Ob[d] * ab + odb * bb;
        }
        ma = mna; mb = mnb;
    }

    if (valid0) {
        float inv = 1.f / la;
        float* op = &out[row0 * D_MODEL + hoff + lane4 * 10];
        #pragma unroll
        for (int i = 0; i < 5; ++i) {
            float2 t; t.x = Oa[lane4*10 + 2*i] * inv; t.y = Oa[lane4*10 + 2*i + 1] * inv;
            *(float2*)(op + 2*i) = t;
        }
    }
    if (valid1) {
        float inv = 1.f / lb;
        float* op = &out[row1 * D_MODEL + hoff + lane4 * 10];
        #pragma unroll
        for (int i = 0; i < 5; ++i) {
            float2 t; t.x = Ob[lane4*10 + 2*i] * inv; t.y = Ob[lane4*10 + 2*i + 1] * inv;
            *(float2*)(op + 2*i) = t;
        }
    }
}

extern "C" void kernel_launch(void* const* d_in, const int* in_sizes, int n_in,
                              void* d_out, int out_size) {
    const float* x     = (const float*)d_in[0];
    const float* gmask = (const float*)d_in[1];
    const float* Wq    = (const float*)d_in[2];
    const float* Wk    = (const float*)d_in[3];
    const float* Wv    = (const float*)d_in[4];
    const float* Wo    = (const float*)d_in[5];
    const float* bo    = (const float*)d_in[6];
    float* out = (float*)d_out;

    float *Qp, *Vp, *Ap, *vmp, *pp; __half* Khp;
    int *cp, *klp, *kcp, *qlp, *qcp;
    cudaGetSymbolAddress((void**)&Qp, g_Q);
    cudaGetSymbolAddress((void**)&Khp, g_Kh);
    cudaGetSymbolAddress((void**)&Vp, g_V);
    cudaGetSymbolAddress((void**)&Ap, g_A);
    cudaGetSymbolAddress((void**)&vmp, g_vmean);
    cudaGetSymbolAddress((void**)&pp, g_part);
    cudaGetSymbolAddress((void**)&cp, g_code);
    cudaGetSymbolAddress((void**)&klp, g_klist);
    cudaGetSymbolAddress((void**)&kcp, g_kcount);
    cudaGetSymbolAddress((void**)&qlp, g_qlist);
    cudaGetSymbolAddress((void**)&qcp, g_qcount);

    code_kernel<<<16, 256>>>(gmask, cp);
    build_lists<<<7, 256>>>(cp, klp, kcp, qlp, qcp);
    gemm64_qkv<<<dim3(D_MODEL / 64, N_TOK / 64, 3), 256>>>(x, Wq, Wk, Wv, Qp, Khp, Vp);
    attn_kernel<<<dim3(7 * 16, HEADS), 128>>>(Qp, Khp, Vp, klp, kcp, qlp, qcp, Ap);
    vmean1<<<32, 320>>>(Vp, pp);
    vmean2<<<1, 320>>>(pp, vmp);
    fill_inactive<<<N_TOK, 64>>>(cp, vmp, Ap);
    gemm64<<<dim3(D_MODEL / 64, N_TOK / 64), 256>>>(Ap, Wo, bo, out, N_TOK, D_MODEL, D_MODEL);
}

// round 13
// speedup vs baseline: 2.1320x; 1.3909x over previous
#include <cuda_runtime.h>
#include <cuda_fp16.h>
#include <math.h>

#define N_TOK 4096
#define D_MODEL 320
#define HEADS 8
#define DH 40
#define SCALE 0.15811388300841897f  // 40^-0.5
#define NEG_BIG  (-3.0e38f)
#define M_INIT   (-1.0e37f)
#define SPLIT_TILES 8               // key-tiles (of 64 keys) per split block
#define NSPLIT_MAX 8
#define QSLOTS 1024                 // max qslots per class (16 qtiles x 64)
#define SLOT_TOT (7 * QSLOTS)       // 7168

// ---------------- scratch (no allocs allowed) ----------------
__device__ float  g_Q[N_TOK * D_MODEL];
__device__ __half g_Kh[N_TOK * D_MODEL];
__device__ float  g_V[N_TOK * D_MODEL];
__device__ float  g_A[N_TOK * D_MODEL];
__device__ int    g_code[N_TOK];
__device__ float  g_vmean[D_MODEL];
__device__ float  g_part[32 * D_MODEL];
__device__ int    g_klist[7 * N_TOK];
__device__ int    g_kcount[7];
__device__ int    g_qlist[7 * N_TOK];
__device__ int    g_qcount[7];
// split-K partials, compact: per head, per (cls,qslot) slot, per split.
// ml: [h][slot][split][2]  (m,l interleaved) ; O: [h][slot][split][DH]
// Only slots with qslot < qcount and splits < nsplits(cls) are written/read.
__device__ float  g_pml[HEADS * SLOT_TOT * NSPLIT_MAX * 2];   // ~4.6 MB
__device__ float  g_pO[(size_t)HEADS * SLOT_TOT * NSPLIT_MAX * DH]; // ~73 MB -> see note
// note: DH=40 floats * 8 splits * 7168 slots * 8 heads = 73MB; keep but this is
// a __device__ global (static footprint, no runtime alloc).

// ---------------- cp.async helpers ----------------
__device__ __forceinline__ void cp_async16(void* smem, const void* gmem) {
    unsigned sa = (unsigned)__cvta_generic_to_shared(smem);
    asm volatile("cp.async.cg.shared.global [%0], [%1], 16;" :: "r"(sa), "l"(gmem));
}
__device__ __forceinline__ void cp_commit() {
    asm volatile("cp.async.commit_group;");
}
template<int N> __device__ __forceinline__ void cp_wait() {
    asm volatile("cp.async.wait_group %0;" :: "n"(N));
}

// ---------------- phase-code kernel ----------------
__global__ void code_kernel(const float* __restrict__ g, int* __restrict__ code) {
    int i = blockIdx.x * 256 + threadIdx.x;
    if (i < N_TOK) {
        int c = 0;
        if (g[i]           > 0.5f) c |= 1;
        if (g[N_TOK + i]   > 0.5f) c |= 2;
        if (g[2*N_TOK + i] > 0.5f) c |= 4;
        code[i] = c;
    }
}

// ---------------- deterministic per-class list compaction (ballot scan) ----------------
__global__ __launch_bounds__(256) void build_lists(
    const int* __restrict__ code,
    int* __restrict__ klist, int* __restrict__ kcount,
    int* __restrict__ qlist, int* __restrict__ qcount)
{
    int c = blockIdx.x + 1;
    int tid = threadIdx.x;
    int lane = tid & 31, wid = tid >> 5;
    __shared__ int wk[8], wq[8];
    __shared__ int kbase, qbase;
    if (tid == 0) { kbase = 0; qbase = 0; }
    __syncthreads();

    int loff = (c - 1) * N_TOK;
    for (int t0 = 0; t0 < N_TOK; t0 += 256) {
        int i = t0 + tid;
        int ci = code[i];
        int kp = (ci & c) ? 1 : 0;
        int qp = (ci == c) ? 1 : 0;

        unsigned kb = __ballot_sync(0xffffffffu, kp);
        unsigned qb = __ballot_sync(0xffffffffu, qp);
        int kpre = __popc(kb & ((1u << lane) - 1));
        int qpre = __popc(qb & ((1u << lane) - 1));
        if (lane == 0) { wk[wid] = __popc(kb); wq[wid] = __popc(qb); }
        __syncthreads();
        if (tid == 0) {
            int rk = kbase, rq = qbase;
            #pragma unroll
            for (int w = 0; w < 8; ++w) {
                int tk = wk[w]; wk[w] = rk; rk += tk;
                int tq = wq[w]; wq[w] = rq; rq += tq;
            }
            kbase = rk; qbase = rq;
        }
        __syncthreads();
        if (kp) klist[loff + wk[wid] + kpre] = i;
        if (qp) qlist[loff + wq[wid] + qpre] = i;
        __syncthreads();
    }
    if (tid == 0) { kcount[c - 1] = kbase; qcount[c - 1] = qbase; }
}

// ---------------- coalesced 2-stage column mean of V ----------------
__global__ void vmean1(const float* __restrict__ V, float* __restrict__ part) {
    int b = blockIdx.x;
    int c = threadIdx.x;
    float s = 0.f;
    int r0 = b * 128;
    #pragma unroll 4
    for (int r = 0; r < 128; ++r) s += V[(r0 + r) * D_MODEL + c];
    part[b * D_MODEL + c] = s;
}
__global__ void vmean2(const float* __restrict__ part, float* __restrict__ vm) {
    int c = threadIdx.x;
    float s = 0.f;
    #pragma unroll
    for (int b = 0; b < 32; ++b) s += part[b * D_MODEL + c];
    vm[c] = s * (1.f / (float)N_TOK);
}

// ---------------- fully-masked rows -> vmean ----------------
__global__ void fill_inactive(const int* __restrict__ code,
                              const float* __restrict__ vmean,
                              float* __restrict__ A) {
    int row = blockIdx.x;
    if (code[row] != 0) return;
    for (int d = threadIdx.x; d < D_MODEL; d += 64)
        A[row * D_MODEL + d] = vmean[d];
}

// ---------------- tiled fp32 GEMM body (optional fp16 output) ----------------
template<bool HALF_OUT>
__device__ __forceinline__ void gemm64_body(
    const float* __restrict__ A, const float* __restrict__ B,
    const float* __restrict__ bias, void* __restrict__ C,
    int M, int N, int K, int m0, int n0)
{
    __shared__ float As[16][68];
    __shared__ float Bs[16][68];
    int tid = threadIdx.x;
    int ty = tid >> 4, tx = tid & 15;

    int lr = tid >> 2;
    int lk = (tid & 3) * 4;
    int bk = tid >> 4;
    int bc = (tid & 15) * 4;

    float acc[4][4];
    #pragma unroll
    for (int i = 0; i < 4; ++i)
        #pragma unroll
        for (int j = 0; j < 4; ++j) acc[i][j] = 0.f;

    for (int k0 = 0; k0 < K; k0 += 16) {
        float4 av = *(const float4*)&A[(m0 + lr) * K + k0 + lk];
        As[lk + 0][lr] = av.x; As[lk + 1][lr] = av.y;
        As[lk + 2][lr] = av.z; As[lk + 3][lr] = av.w;
        float4 bv = *(const float4*)&B[(k0 + bk) * N + n0 + bc];
        *(float4*)&Bs[bk][bc] = bv;
        __syncthreads();
        #pragma unroll
        for (int kk = 0; kk < 16; ++kk) {
            float a[4], b[4];
            #pragma unroll
            for (int i = 0; i < 4; ++i) a[i] = As[kk][ty * 4 + i];
            #pragma unroll
            for (int j = 0; j < 4; ++j) b[j] = Bs[kk][tx * 4 + j];
            #pragma unroll
            for (int i = 0; i < 4; ++i)
                #pragma unroll
                for (int j = 0; j < 4; ++j)
                    acc[i][j] = fmaf(a[i], b[j], acc[i][j]);
        }
        __syncthreads();
    }
    #pragma unroll
    for (int i = 0; i < 4; ++i) {
        int row = m0 + ty * 4 + i;
        #pragma unroll
        for (int j = 0; j < 4; ++j) {
            int col = n0 + tx * 4 + j;
            float v = acc[i][j];
            if (bias) v += bias[col];
            if (HALF_OUT) ((__half*)C)[row * N + col] = __float2half(v);
            else          ((float*)C)[row * N + col] = v;
        }
    }
}

__global__ __launch_bounds__(256) void gemm64(
    const float* __restrict__ A, const float* __restrict__ B,
    const float* __restrict__ bias, float* __restrict__ C,
    int M, int N, int K)
{
    gemm64_body<false>(A, B, bias, C, M, N, K, blockIdx.y * 64, blockIdx.x * 64);
}

__global__ __launch_bounds__(256) void gemm64_qkv(
    const float* __restrict__ A,
    const float* __restrict__ Wq, const float* __restrict__ Wk,
    const float* __restrict__ Wv,
    float* __restrict__ Q, __half* __restrict__ Kh, float* __restrict__ V)
{
    int m0 = blockIdx.y * 64, n0 = blockIdx.x * 64;
    if (blockIdx.z == 0)
        gemm64_body<false>(A, Wq, nullptr, Q, N_TOK, D_MODEL, D_MODEL, m0, n0);
    else if (blockIdx.z == 1)
        gemm64_body<true>(A, Wk, nullptr, Kh, N_TOK, D_MODEL, D_MODEL, m0, n0);
    else
        gemm64_body<false>(A, Wv, nullptr, V, N_TOK, D_MODEL, D_MODEL, m0, n0);
}

// ---------------- split-K class-compacted flash attention ----------------
// grid (7*16 qtiles, 8 heads, 8 splits). Each block handles <= SPLIT_TILES
// key-tiles of its (class, qtile, head) and writes partial (m,l,O) to gmem.
// 128 threads = 32 groups x 4 key-lanes, 2 query rows per thread.
__global__ __launch_bounds__(128, 3) void attn_kernel(
    const float* __restrict__ Q, const __half* __restrict__ Kh,
    const float* __restrict__ Vm,
    const int* __restrict__ klist, const int* __restrict__ kcount,
    const int* __restrict__ qlist, const int* __restrict__ qcount,
    float* __restrict__ pml, float* __restrict__ pO)
{
    int grpIdx = blockIdx.x >> 4;
    int cls = (0x3105426 >> (grpIdx * 4)) & 7;    // heavy classes first
    int qt  = blockIdx.x & 15;
    int h   = blockIdx.y;
    int split = blockIdx.z;
    int nQ = qcount[cls];
    if (qt * 64 >= nQ) return;
    int nK = kcount[cls];
    int ntiles = (nK + 63) >> 6;
    int t0 = split * SPLIT_TILES;
    if (t0 >= ntiles) return;
    int t1 = t0 + SPLIT_TILES; if (t1 > ntiles) t1 = ntiles;

    int tid = threadIdx.x;
    int grp = tid >> 2, lane4 = tid & 3;
    int qslot0 = qt * 64 + grp;
    int qslot1 = qslot0 + 32;
    bool valid0 = qslot0 < nQ;
    bool valid1 = qslot1 < nQ;
    int row0 = valid0 ? qlist[cls * N_TOK + qslot0] : qlist[cls * N_TOK];
    int row1 = valid1 ? qlist[cls * N_TOK + qslot1] : qlist[cls * N_TOK];
    int hoff = h * DH;

    __shared__ __half Ksm[2][64 * DH];
    __shared__ float  Vsm[2][64 * DH];

    __half2 qa[20], qb[20];
    #pragma unroll
    for (int d4 = 0; d4 < 10; ++d4) {
        float4 t = *(const float4*)&Q[row0 * D_MODEL + hoff + d4 * 4];
        qa[d4*2+0] = __floats2half2_rn(t.x, t.y);
        qa[d4*2+1] = __floats2half2_rn(t.z, t.w);
        float4 u = *(const float4*)&Q[row1 * D_MODEL + hoff + d4 * 4];
        qb[d4*2+0] = __floats2half2_rn(u.x, u.y);
        qb[d4*2+1] = __floats2half2_rn(u.z, u.w);
    }

    float ma = M_INIT, la = 0.f, mb = M_INIT, lb = 0.f;
    float Oa[DH], Ob[DH];
    #pragma unroll
    for (int d = 0; d < DH; ++d) { Oa[d] = 0.f; Ob[d] = 0.f; }

    const int* kl = klist + cls * N_TOK;

    // prefetch first tile of this split
    {
        int base = t0 << 6;
        int nloc = nK - base; if (nloc > 64) nloc = 64;
        for (int v2 = tid; v2 < 320; v2 += 128) {
            int r = v2 / 5, c = v2 - r * 5;
            if (r < nloc) {
                int j = kl[base + r];
                cp_async16(&Ksm[0][r * DH + c * 8], Kh + j * D_MODEL + hoff + c * 8);
            }
        }
        for (int v2 = tid; v2 < 640; v2 += 128) {
            int r = v2 / 10, c = v2 - r * 10;
            if (r < nloc) {
                int j = kl[base + r];
                cp_async16(&Vsm[0][r * DH + c * 4], Vm + j * D_MODEL + hoff + c * 4);
            }
        }
        cp_commit();
    }

    for (int kt = t0; kt < t1; ++kt) {
        int buf = (kt - t0) & 1;
        int base = kt << 6;
        int nloc = nK - base; if (nloc > 64) nloc = 64;

        if (kt + 1 < t1) {
            int base2 = base + 64;
            int nloc2 = nK - base2; if (nloc2 > 64) nloc2 = 64;
            __half* Kb2 = Ksm[buf ^ 1];
            float*  Vb2 = Vsm[buf ^ 1];
            for (int v2 = tid; v2 < 320; v2 += 128) {
                int r = v2 / 5, c = v2 - r * 5;
                if (r < nloc2) {
                    int j = kl[base2 + r];
                    cp_async16(&Kb2[r * DH + c * 8], Kh + j * D_MODEL + hoff + c * 8);
                }
            }
            for (int v2 = tid; v2 < 640; v2 += 128) {
                int r = v2 / 10, c = v2 - r * 10;
                if (r < nloc2) {
                    int j = kl[base2 + r];
                    cp_async16(&Vb2[r * DH + c * 4], Vm + j * D_MODEL + hoff + c * 4);
                }
            }
            cp_commit();
            cp_wait<1>();
        } else {
            cp_wait<0>();
        }
        __syncthreads();

        const __half* Kb = Ksm[buf];
        const float*  Vb = Vsm[buf];

        #pragma unroll 1
        for (int ch = 0; ch < 4; ++ch) {
            int j0 = ch << 4;
            float sa[4], sb[4];
            #pragma unroll
            for (int s = 0; s < 4; ++s) {
                int jj = j0 | (s << 2) | lane4;
                const float4* kp = (const float4*)(Kb + jj * DH);
                __half2 a0 = __float2half2_rn(0.f), a1 = a0, a2 = a0, a3 = a0;
                __half2 b0 = a0, b1 = a0, b2 = a0, b3 = a0;
                #pragma unroll
                for (int c = 0; c < 5; ++c) {
                    float4 kv = kp[c];
                    __half2 k0 = *(const __half2*)&kv.x;
                    __half2 k1 = *(const __half2*)&kv.y;
                    __half2 k2 = *(const __half2*)&kv.z;
                    __half2 k3 = *(const __half2*)&kv.w;
                    a0 = __hfma2(qa[c*4+0], k0, a0);  b0 = __hfma2(qb[c*4+0], k0, b0);
                    a1 = __hfma2(qa[c*4+1], k1, a1);  b1 = __hfma2(qb[c*4+1], k1, b1);
                    a2 = __hfma2(qa[c*4+2], k2, a2);  b2 = __hfma2(qb[c*4+2], k2, b2);
                    a3 = __hfma2(qa[c*4+3], k3, a3);  b3 = __hfma2(qb[c*4+3], k3, b3);
                }
                __half2 ssa = __hadd2(__hadd2(a0, a1), __hadd2(a2, a3));
                __half2 ssb = __hadd2(__hadd2(b0, b1), __hadd2(b2, b3));
                float2 fa = __half22float2(ssa);
                float2 fb = __half22float2(ssb);
                bool ok = jj < nloc;
                sa[s] = ok ? (fa.x + fa.y) * SCALE : NEG_BIG;
                sb[s] = ok ? (fb.x + fb.y) * SCALE : NEG_BIG;
            }
            float tma = fmaxf(fmaxf(sa[0], sa[1]), fmaxf(sa[2], sa[3]));
            float tmb = fmaxf(fmaxf(sb[0], sb[1]), fmaxf(sb[2], sb[3]));
            float mna = fmaxf(ma, tma);
            float mnb = fmaxf(mb, tmb);
            float fa = __expf(ma - mna);
            float fb = __expf(mb - mnb);
            ma = mna; mb = mnb;
            la *= fa; lb *= fb;
            #pragma unroll
            for (int d = 0; d < DH; ++d) { Oa[d] *= fa; Ob[d] *= fb; }
            #pragma unroll
            for (int s = 0; s < 4; ++s) {
                int jj = j0 | (s << 2) | lane4;
                float pa = __expf(sa[s] - ma);
                float pb = __expf(sb[s] - mb);
                la += pa; lb += pb;
                const float4* vp = (const float4*)(Vb + jj * DH);
                #pragma unroll
                for (int d4 = 0; d4 < 10; ++d4) {
                    float4 vv = vp[d4];
                    Oa[d4*4+0] = fmaf(pa, vv.x, Oa[d4*4+0]);
                    Ob[d4*4+0] = fmaf(pb, vv.x, Ob[d4*4+0]);
                    Oa[d4*4+1] = fmaf(pa, vv.y, Oa[d4*4+1]);
                    Ob[d4*4+1] = fmaf(pb, vv.y, Ob[d4*4+1]);
                    Oa[d4*4+2] = fmaf(pa, vv.z, Oa[d4*4+2]);
                    Ob[d4*4+2] = fmaf(pb, vv.z, Ob[d4*4+2]);
                    Oa[d4*4+3] = fmaf(pa, vv.w, Oa[d4*4+3]);
                    Ob[d4*4+3] = fmaf(pb, vv.w, Ob[d4*4+3]);
                }
            }
        }
        __syncthreads();
    }

    // merge across the 4 lanes of each group (both rows)
    #pragma unroll
    for (int off = 1; off < 4; off <<= 1) {
        float moa = __shfl_xor_sync(0xffffffffu, ma, off);
        float loa = __shfl_xor_sync(0xffffffffu, la, off);
        float mob = __shfl_xor_sync(0xffffffffu, mb, off);
        float lob = __shfl_xor_sync(0xffffffffu, lb, off);
        float mna = fmaxf(ma, moa);
        float mnb = fmaxf(mb, mob);
        float aa = __expf(ma - mna), ba = __expf(moa - mna);
        float ab = __expf(mb - mnb), bb = __expf(mob - mnb);
        la = la * aa + loa * ba;
        lb = lb * ab + lob * bb;
        #pragma unroll
        for (int d = 0; d < DH; ++d) {
            float oda = __shfl_xor_sync(0xffffffffu, Oa[d], off);
            float odb = __shfl_xor_sync(0xffffffffu, Ob[d], off);
            Oa[d] = Oa[d] * aa + oda * ba;
            Ob[d] = Ob[d] * ab + odb * bb;
        }
        ma = mna; mb = mnb;
    }

    // write split partials (compact layout: [h][slot][split])
    if (valid0) {
        size_t slot = (size_t)h * SLOT_TOT + cls * QSLOTS + qslot0;
        size_t ps = slot * NSPLIT_MAX + split;
        if (lane4 == 0) { pml[ps * 2] = ma; pml[ps * 2 + 1] = la; }
        float* op = pO + ps * DH + lane4 * 10;
        #pragma unroll
        for (int i = 0; i < 5; ++i)
            *(float2*)(op + 2*i) = make_float2(Oa[lane4*10 + 2*i], Oa[lane4*10 + 2*i + 1]);
    }
    if (valid1) {
        size_t slot = (size_t)h * SLOT_TOT + cls * QSLOTS + qslot1;
        size_t ps = slot * NSPLIT_MAX + split;
        if (lane4 == 0) { pml[ps * 2] = mb; pml[ps * 2 + 1] = lb; }
        float* op = pO + ps * DH + lane4 * 10;
        #pragma unroll
        for (int i = 0; i < 5; ++i)
            *(float2*)(op + 2*i) = make_float2(Ob[lane4*10 + 2*i], Ob[lane4*10 + 2*i + 1]);
    }
}

// ---------------- split-K merge ----------------
// grid (7*16 qtiles, 8 heads), 256 threads = 64 rows x 4 dim-lanes.
__global__ __launch_bounds__(256) void merge_attn(
    const float* __restrict__ pml, const float* __restrict__ pO,
    const int* __restrict__ kcount, const int* __restrict__ qcount,
    const int* __restrict__ qlist, float* __restrict__ out)
{
    int cls = blockIdx.x >> 4;
    int qt  = blockIdx.x & 15;
    int h   = blockIdx.y;
    int nQ = qcount[cls];
    if (qt * 64 >= nQ) return;
    int nK = kcount[cls];
    int ntiles = (nK + 63) >> 6;
    int nsplits = (ntiles + SPLIT_TILES - 1) / SPLIT_TILES;

    int tid = threadIdx.x;
    int grp = tid >> 2, lane4 = tid & 3;
    int qslot = qt * 64 + grp;
    if (qslot >= nQ) return;
    int row = qlist[cls * N_TOK + qslot];
    size_t slot = (size_t)h * SLOT_TOT + cls * QSLOTS + qslot;

    float M = M_INIT;
    for (int s = 0; s < nsplits; ++s)
        M = fmaxf(M, pml[(slot * NSPLIT_MAX + s) * 2]);

    float L = 0.f;
    float Od[10];
    #pragma unroll
    for (int i = 0; i < 10; ++i) Od[i] = 0.f;

    for (int s = 0; s < nsplits; ++s) {
        size_t ps = slot * NSPLIT_MAX + s;
        float w = __expf(pml[ps * 2] - M);
        L += pml[ps * 2 + 1] * w;
        const float* op = pO + ps * DH + lane4 * 10;
        #pragma unroll
        for (int i = 0; i < 5; ++i) {
            float2 t = *(const float2*)(op + 2*i);
            Od[2*i]   = fmaf(t.x, w, Od[2*i]);
            Od[2*i+1] = fmaf(t.y, w, Od[2*i+1]);
        }
    }
    float inv = 1.f / L;
    float* dst = &out[row * D_MODEL + h * DH + lane4 * 10];
    #pragma unroll
    for (int i = 0; i < 5; ++i)
        *(float2*)(dst + 2*i) = make_float2(Od[2*i] * inv, Od[2*i+1] * inv);
}

extern "C" void kernel_launch(void* const* d_in, const int* in_sizes, int n_in,
                              void* d_out, int out_size) {
    const float* x     = (const float*)d_in[0];
    const float* gmask = (const float*)d_in[1];
    const float* Wq    = (const float*)d_in[2];
    const float* Wk    = (const float*)d_in[3];
    const float* Wv    = (const float*)d_in[4];
    const float* Wo    = (const float*)d_in[5];
    const float* bo    = (const float*)d_in[6];
    float* out = (float*)d_out;

    float *Qp, *Vp, *Ap, *vmp, *pp, *pmlp, *pOp; __half* Khp;
    int *cp, *klp, *kcp, *qlp, *qcp;
    cudaGetSymbolAddress((void**)&Qp, g_Q);
    cudaGetSymbolAddress((void**)&Khp, g_Kh);
    cudaGetSymbolAddress((void**)&Vp, g_V);
    cudaGetSymbolAddress((void**)&Ap, g_A);
    cudaGetSymbolAddress((void**)&vmp, g_vmean);
    cudaGetSymbolAddress((void**)&pp, g_part);
    cudaGetSymbolAddress((void**)&cp, g_code);
    cudaGetSymbolAddress((void**)&klp, g_klist);
    cudaGetSymbolAddress((void**)&kcp, g_kcount);
    cudaGetSymbolAddress((void**)&qlp, g_qlist);
    cudaGetSymbolAddress((void**)&qcp, g_qcount);
    cudaGetSymbolAddress((void**)&pmlp, g_pml);
    cudaGetSymbolAddress((void**)&pOp, g_pO);

    code_kernel<<<16, 256>>>(gmask, cp);
    build_lists<<<7, 256>>>(cp, klp, kcp, qlp, qcp);
    gemm64_qkv<<<dim3(D_MODEL / 64, N_TOK / 64, 3), 256>>>(x, Wq, Wk, Wv, Qp, Khp, Vp);
    attn_kernel<<<dim3(7 * 16, HEADS, NSPLIT_MAX), 128>>>(
        Qp, Khp, Vp, klp, kcp, qlp, qcp, pmlp, pOp);
    merge_attn<<<dim3(7 * 16, HEADS), 256>>>(pmlp, pOp, kcp, qcp, qlp, Ap);
    vmean1<<<32, 320>>>(Vp, pp);
    vmean2<<<1, 320>>>(pp, vmp);
    fill_inactive<<<N_TOK, 64>>>(cp, vmp, Ap);
    gemm64<<<dim3(D_MODEL / 64, N_TOK / 64), 256>>>(Ap, Wo, bo, out, N_TOK, D_MODEL, D_MODEL);
}

// round 14
// speedup vs baseline: 2.8297x; 1.3273x over previous
#include <cuda_runtime.h>
#include <cuda_fp16.h>
#include <math.h>

#define N_TOK 4096
#define D_MODEL 320
#define HEADS 8
#define DH 40
#define SCALE 0.15811388300841897f  // 40^-0.5
#define C2EXP 0.22811011f           // SCALE * log2(e)
#define SPLIT_TILES 8               // key-tiles (of 64 keys) per split block
#define NSPLIT_MAX 8
#define QSLOTS 1024                 // max qslots per class (16 qtiles x 64)
#define SLOT_TOT (7 * QSLOTS)       // 7168

// ---------------- scratch (no allocs allowed) ----------------
__device__ float  g_Q[N_TOK * D_MODEL];
__device__ __half g_Kh[N_TOK * D_MODEL];
__device__ float  g_V[N_TOK * D_MODEL];
__device__ float  g_A[N_TOK * D_MODEL];
__device__ int    g_code[N_TOK];
__device__ float  g_vmean[D_MODEL];
__device__ float  g_part[32 * D_MODEL];
__device__ int    g_klist[7 * N_TOK];
__device__ int    g_kcount[7];
__device__ int    g_qlist[7 * N_TOK];
__device__ int    g_qcount[7];
// split-K partials (no max needed -- plain sums): l and O per [h][slot][split]
__device__ float  g_pl[HEADS * SLOT_TOT * NSPLIT_MAX];
__device__ float  g_pO[(size_t)HEADS * SLOT_TOT * NSPLIT_MAX * DH];

// ---------------- cp.async / packed-math helpers ----------------
__device__ __forceinline__ void cp_async16(void* smem, const void* gmem) {
    unsigned sa = (unsigned)__cvta_generic_to_shared(smem);
    asm volatile("cp.async.cg.shared.global [%0], [%1], 16;" :: "r"(sa), "l"(gmem));
}
__device__ __forceinline__ void cp_commit() {
    asm volatile("cp.async.commit_group;");
}
template<int N> __device__ __forceinline__ void cp_wait() {
    asm volatile("cp.async.wait_group %0;" :: "n"(N));
}
__device__ __forceinline__ float fast_exp2(float x) {
    float y;
    asm("ex2.approx.ftz.f32 %0, %1;" : "=f"(y) : "f"(x));
    return y;
}
__device__ __forceinline__ unsigned long long pack_dup(float x) {
    unsigned long long r;
    unsigned u = __float_as_uint(x);
    asm("mov.b64 %0, {%1, %2};" : "=l"(r) : "r"(u), "r"(u));
    return r;
}
__device__ __forceinline__ void ffma2(unsigned long long& acc,
                                      unsigned long long v, unsigned long long p) {
    asm("fma.rn.f32x2 %0, %1, %2, %3;" : "=l"(acc) : "l"(v), "l"(p), "l"(acc));
}
__device__ __forceinline__ unsigned long long addf2(unsigned long long a,
                                                    unsigned long long b) {
    unsigned long long r;
    asm("add.rn.f32x2 %0, %1, %2;" : "=l"(r) : "l"(a), "l"(b));
    return r;
}

// ---------------- phase-code kernel ----------------
__global__ void code_kernel(const float* __restrict__ g, int* __restrict__ code) {
    int i = blockIdx.x * 256 + threadIdx.x;
    if (i < N_TOK) {
        int c = 0;
        if (g[i]           > 0.5f) c |= 1;
        if (g[N_TOK + i]   > 0.5f) c |= 2;
        if (g[2*N_TOK + i] > 0.5f) c |= 4;
        code[i] = c;
    }
}

// ---------------- deterministic per-class list compaction (ballot scan) ----------------
__global__ __launch_bounds__(256) void build_lists(
    const int* __restrict__ code,
    int* __restrict__ klist, int* __restrict__ kcount,
    int* __restrict__ qlist, int* __restrict__ qcount)
{
    int c = blockIdx.x + 1;
    int tid = threadIdx.x;
    int lane = tid & 31, wid = tid >> 5;
    __shared__ int wk[8], wq[8];
    __shared__ int kbase, qbase;
    if (tid == 0) { kbase = 0; qbase = 0; }
    __syncthreads();

    int loff = (c - 1) * N_TOK;
    for (int t0 = 0; t0 < N_TOK; t0 += 256) {
        int i = t0 + tid;
        int ci = code[i];
        int kp = (ci & c) ? 1 : 0;
        int qp = (ci == c) ? 1 : 0;

        unsigned kb = __ballot_sync(0xffffffffu, kp);
        unsigned qb = __ballot_sync(0xffffffffu, qp);
        int kpre = __popc(kb & ((1u << lane) - 1));
        int qpre = __popc(qb & ((1u << lane) - 1));
        if (lane == 0) { wk[wid] = __popc(kb); wq[wid] = __popc(qb); }
        __syncthreads();
        if (tid == 0) {
            int rk = kbase, rq = qbase;
            #pragma unroll
            for (int w = 0; w < 8; ++w) {
                int tk = wk[w]; wk[w] = rk; rk += tk;
                int tq = wq[w]; wq[w] = rq; rq += tq;
            }
            kbase = rk; qbase = rq;
        }
        __syncthreads();
        if (kp) klist[loff + wk[wid] + kpre] = i;
        if (qp) qlist[loff + wq[wid] + qpre] = i;
        __syncthreads();
    }
    if (tid == 0) { kcount[c - 1] = kbase; qcount[c - 1] = qbase; }
}

// ---------------- coalesced 2-stage column mean of V ----------------
__global__ void vmean1(const float* __restrict__ V, float* __restrict__ part) {
    int b = blockIdx.x;
    int c = threadIdx.x;
    float s = 0.f;
    int r0 = b * 128;
    #pragma unroll 4
    for (int r = 0; r < 128; ++r) s += V[(r0 + r) * D_MODEL + c];
    part[b * D_MODEL + c] = s;
}
__global__ void vmean2(const float* __restrict__ part, float* __restrict__ vm) {
    int c = threadIdx.x;
    float s = 0.f;
    #pragma unroll
    for (int b = 0; b < 32; ++b) s += part[b * D_MODEL + c];
    vm[c] = s * (1.f / (float)N_TOK);
}

// ---------------- fully-masked rows -> vmean ----------------
__global__ void fill_inactive(const int* __restrict__ code,
                              const float* __restrict__ vmean,
                              float* __restrict__ A) {
    int row = blockIdx.x;
    if (code[row] != 0) return;
    for (int d = threadIdx.x; d < D_MODEL; d += 64)
        A[row * D_MODEL + d] = vmean[d];
}

// ---------------- tiled fp32 GEMM body (optional fp16 output) ----------------
template<bool HALF_OUT>
__device__ __forceinline__ void gemm64_body(
    const float* __restrict__ A, const float* __restrict__ B,
    const float* __restrict__ bias, void* __restrict__ C,
    int M, int N, int K, int m0, int n0)
{
    __shared__ float As[16][68];
    __shared__ float Bs[16][68];
    int tid = threadIdx.x;
    int ty = tid >> 4, tx = tid & 15;

    int lr = tid >> 2;
    int lk = (tid & 3) * 4;
    int bk = tid >> 4;
    int bc = (tid & 15) * 4;

    float acc[4][4];
    #pragma unroll
    for (int i = 0; i < 4; ++i)
        #pragma unroll
        for (int j = 0; j < 4; ++j) acc[i][j] = 0.f;

    for (int k0 = 0; k0 < K; k0 += 16) {
        float4 av = *(const float4*)&A[(m0 + lr) * K + k0 + lk];
        As[lk + 0][lr] = av.x; As[lk + 1][lr] = av.y;
        As[lk + 2][lr] = av.z; As[lk + 3][lr] = av.w;
        float4 bv = *(const float4*)&B[(k0 + bk) * N + n0 + bc];
        *(float4*)&Bs[bk][bc] = bv;
        __syncthreads();
        #pragma unroll
        for (int kk = 0; kk < 16; ++kk) {
            float a[4], b[4];
            #pragma unroll
            for (int i = 0; i < 4; ++i) a[i] = As[kk][ty * 4 + i];
            #pragma unroll
            for (int j = 0; j < 4; ++j) b[j] = Bs[kk][tx * 4 + j];
            #pragma unroll
            for (int i = 0; i < 4; ++i)
                #pragma unroll
                for (int j = 0; j < 4; ++j)
                    acc[i][j] = fmaf(a[i], b[j], acc[i][j]);
        }
        __syncthreads();
    }
    #pragma unroll
    for (int i = 0; i < 4; ++i) {
        int row = m0 + ty * 4 + i;
        #pragma unroll
        for (int j = 0; j < 4; ++j) {
            int col = n0 + tx * 4 + j;
            float v = acc[i][j];
            if (bias) v += bias[col];
            if (HALF_OUT) ((__half*)C)[row * N + col] = __float2half(v);
            else          ((float*)C)[row * N + col] = v;
        }
    }
}

__global__ __launch_bounds__(256) void gemm64(
    const float* __restrict__ A, const float* __restrict__ B,
    const float* __restrict__ bias, float* __restrict__ C,
    int M, int N, int K)
{
    gemm64_body<false>(A, B, bias, C, M, N, K, blockIdx.y * 64, blockIdx.x * 64);
}

__global__ __launch_bounds__(256) void gemm64_qkv(
    const float* __restrict__ A,
    const float* __restrict__ Wq, const float* __restrict__ Wk,
    const float* __restrict__ Wv,
    float* __restrict__ Q, __half* __restrict__ Kh, float* __restrict__ V)
{
    int m0 = blockIdx.y * 64, n0 = blockIdx.x * 64;
    if (blockIdx.z == 0)
        gemm64_body<false>(A, Wq, nullptr, Q, N_TOK, D_MODEL, D_MODEL, m0, n0);
    else if (blockIdx.z == 1)
        gemm64_body<true>(A, Wk, nullptr, Kh, N_TOK, D_MODEL, D_MODEL, m0, n0);
    else
        gemm64_body<false>(A, Wv, nullptr, V, N_TOK, D_MODEL, D_MODEL, m0, n0);
}

// ---------------- split-K attention, no-max softmax + FFMA2 ----------------
// Logits are tiny (|s| << 80) -> exp cannot overflow fp32 -> skip online max:
// p = exp2(dot * C2EXP), accumulate l = sum p, O = sum p*V, normalize at end.
// V accumulation uses packed fma.rn.f32x2 (FFMA2): 20 instr/key/row-pair.
// 128 threads = 32 groups x 4 key-lanes, 2 query rows per thread.
__global__ __launch_bounds__(128, 3) void attn_kernel(
    const float* __restrict__ Q, const __half* __restrict__ Kh,
    const float* __restrict__ Vm,
    const int* __restrict__ klist, const int* __restrict__ kcount,
    const int* __restrict__ qlist, const int* __restrict__ qcount,
    float* __restrict__ pl, float* __restrict__ pO)
{
    int grpIdx = blockIdx.x >> 4;
    int cls = (0x3105426 >> (grpIdx * 4)) & 7;    // heavy classes first
    int qt  = blockIdx.x & 15;
    int h   = blockIdx.y;
    int split = blockIdx.z;
    int nQ = qcount[cls];
    if (qt * 64 >= nQ) return;
    int nK = kcount[cls];
    int ntiles = (nK + 63) >> 6;
    int t0 = split * SPLIT_TILES;
    if (t0 >= ntiles) return;
    int t1 = t0 + SPLIT_TILES; if (t1 > ntiles) t1 = ntiles;

    int tid = threadIdx.x;
    int grp = tid >> 2, lane4 = tid & 3;
    int qslot0 = qt * 64 + grp;
    int qslot1 = qslot0 + 32;
    bool valid0 = qslot0 < nQ;
    bool valid1 = qslot1 < nQ;
    int row0 = valid0 ? qlist[cls * N_TOK + qslot0] : qlist[cls * N_TOK];
    int row1 = valid1 ? qlist[cls * N_TOK + qslot1] : qlist[cls * N_TOK];
    int hoff = h * DH;

    __shared__ __align__(16) __half Ksm[2][64 * DH];
    __shared__ __align__(16) float  Vsm[2][64 * DH];

    __half2 qa[20], qb[20];
    #pragma unroll
    for (int d4 = 0; d4 < 10; ++d4) {
        float4 t = *(const float4*)&Q[row0 * D_MODEL + hoff + d4 * 4];
        qa[d4*2+0] = __floats2half2_rn(t.x, t.y);
        qa[d4*2+1] = __floats2half2_rn(t.z, t.w);
        float4 u = *(const float4*)&Q[row1 * D_MODEL + hoff + d4 * 4];
        qb[d4*2+0] = __floats2half2_rn(u.x, u.y);
        qb[d4*2+1] = __floats2half2_rn(u.z, u.w);
    }

    float la = 0.f, lb = 0.f;
    unsigned long long Oa2[20], Ob2[20];   // f32x2 accumulators: 40 dims each row
    #pragma unroll
    for (int d = 0; d < 20; ++d) { Oa2[d] = 0ull; Ob2[d] = 0ull; }

    const int* kl = klist + cls * N_TOK;

    // prefetch first tile of this split (zero-fill V tail rows for NaN safety)
    {
        int base = t0 << 6;
        int nloc = nK - base; if (nloc > 64) nloc = 64;
        for (int v2 = tid; v2 < 320; v2 += 128) {
            int r = v2 / 5, c = v2 - r * 5;
            if (r < nloc) {
                int j = kl[base + r];
                cp_async16(&Ksm[0][r * DH + c * 8], Kh + j * D_MODEL + hoff + c * 8);
            }
        }
        for (int v2 = tid; v2 < 640; v2 += 128) {
            int r = v2 / 10, c = v2 - r * 10;
            if (r < nloc) {
                int j = kl[base + r];
                cp_async16(&Vsm[0][r * DH + c * 4], Vm + j * D_MODEL + hoff + c * 4);
            } else {
                *(float4*)&Vsm[0][r * DH + c * 4] = make_float4(0.f, 0.f, 0.f, 0.f);
            }
        }
        cp_commit();
    }

    for (int kt = t0; kt < t1; ++kt) {
        int buf = (kt - t0) & 1;
        int base = kt << 6;
        int nloc = nK - base; if (nloc > 64) nloc = 64;

        if (kt + 1 < t1) {
            int base2 = base + 64;
            int nloc2 = nK - base2; if (nloc2 > 64) nloc2 = 64;
            __half* Kb2 = Ksm[buf ^ 1];
            float*  Vb2 = Vsm[buf ^ 1];
            for (int v2 = tid; v2 < 320; v2 += 128) {
                int r = v2 / 5, c = v2 - r * 5;
                if (r < nloc2) {
                    int j = kl[base2 + r];
                    cp_async16(&Kb2[r * DH + c * 8], Kh + j * D_MODEL + hoff + c * 8);
                }
            }
            for (int v2 = tid; v2 < 640; v2 += 128) {
                int r = v2 / 10, c = v2 - r * 10;
                if (r < nloc2) {
                    int j = kl[base2 + r];
                    cp_async16(&Vb2[r * DH + c * 4], Vm + j * D_MODEL + hoff + c * 4);
                } else {
                    *(float4*)&Vb2[r * DH + c * 4] = make_float4(0.f, 0.f, 0.f, 0.f);
                }
            }
            cp_commit();
            cp_wait<1>();
        } else {
            cp_wait<0>();
        }
        __syncthreads();

        const __half* Kb = Ksm[buf];
        const float*  Vb = Vsm[buf];

        #pragma unroll 4
        for (int s = 0; s < 16; ++s) {
            int jj = (s << 2) | lane4;   // interleaved: 4 distinct LDS addrs
            // fp16 dot for both rows (K row shared)
            const float4* kp = (const float4*)(Kb + jj * DH);
            __half2 a0 = __float2half2_rn(0.f), a1 = a0, a2 = a0, a3 = a0;
            __half2 b0 = a0, b1 = a0, b2 = a0, b3 = a0;
            #pragma unroll
            for (int c = 0; c < 5; ++c) {
                float4 kv = kp[c];
                __half2 k0 = *(const __half2*)&kv.x;
                __half2 k1 = *(const __half2*)&kv.y;
                __half2 k2 = *(const __half2*)&kv.z;
                __half2 k3 = *(const __half2*)&kv.w;
                a0 = __hfma2(qa[c*4+0], k0, a0);  b0 = __hfma2(qb[c*4+0], k0, b0);
                a1 = __hfma2(qa[c*4+1], k1, a1);  b1 = __hfma2(qb[c*4+1], k1, b1);
                a2 = __hfma2(qa[c*4+2], k2, a2);  b2 = __hfma2(qb[c*4+2], k2, b2);
                a3 = __hfma2(qa[c*4+3], k3, a3);  b3 = __hfma2(qb[c*4+3], k3, b3);
            }
            __half2 ssa = __hadd2(__hadd2(a0, a1), __hadd2(a2, a3));
            __half2 ssb = __hadd2(__hadd2(b0, b1), __hadd2(b2, b3));
            float2 fda = __half22float2(ssa);
            float2 fdb = __half22float2(ssb);
            bool ok = jj < nloc;
            float pa = ok ? fast_exp2((fda.x + fda.y) * C2EXP) : 0.f;
            float pb = ok ? fast_exp2((fdb.x + fdb.y) * C2EXP) : 0.f;
            la += pa; lb += pb;
            unsigned long long ppa = pack_dup(pa);
            unsigned long long ppb = pack_dup(pb);
            const ulonglong2* vp = (const ulonglong2*)(Vb + jj * DH);
            #pragma unroll
            for (int i = 0; i < 10; ++i) {
                ulonglong2 vv = vp[i];       // LDS.128: 4 dims (2 f32x2)
                ffma2(Oa2[2*i],   vv.x, ppa);
                ffma2(Ob2[2*i],   vv.x, ppb);
                ffma2(Oa2[2*i+1], vv.y, ppa);
                ffma2(Ob2[2*i+1], vv.y, ppb);
            }
        }
        __syncthreads();
    }

    // sum (l, O) across the 4 lanes of each group (plain sums: no max)
    #pragma unroll
    for (int off = 1; off < 4; off <<= 1) {
        la += __shfl_xor_sync(0xffffffffu, la, off);
        lb += __shfl_xor_sync(0xffffffffu, lb, off);
        #pragma unroll
        for (int d = 0; d < 20; ++d) {
            unsigned long long oa = __shfl_xor_sync(0xffffffffu, Oa2[d], off);
            unsigned long long ob = __shfl_xor_sync(0xffffffffu, Ob2[d], off);
            Oa2[d] = addf2(Oa2[d], oa);
            Ob2[d] = addf2(Ob2[d], ob);
        }
    }

    // write split partials (lane 0 of each group writes full row)
    if (lane4 == 0) {
        if (valid0) {
            size_t slot = (size_t)h * SLOT_TOT + cls * QSLOTS + qslot0;
            size_t ps = slot * NSPLIT_MAX + split;
            pl[ps] = la;
            ulonglong2* op = (ulonglong2*)(pO + ps * DH);
            #pragma unroll
            for (int i = 0; i < 10; ++i)
                op[i] = make_ulonglong2(Oa2[2*i], Oa2[2*i+1]);
        }
        if (valid1) {
            size_t slot = (size_t)h * SLOT_TOT + cls * QSLOTS + qslot1;
            size_t ps = slot * NSPLIT_MAX + split;
            pl[ps] = lb;
            ulonglong2* op = (ulonglong2*)(pO + ps * DH);
            #pragma unroll
            for (int i = 0; i < 10; ++i)
                op[i] = make_ulonglong2(Ob2[2*i], Ob2[2*i+1]);
        }
    }
}

// ---------------- split-K merge (plain sums) ----------------
// grid (7*16 qtiles, 8 heads), 256 threads = 64 rows x 4 dim-lanes.
__global__ __launch_bounds__(256) void merge_attn(
    const float* __restrict__ pl, const float* __restrict__ pO,
    const int* __restrict__ kcount, const int* __restrict__ qcount,
    const int* __restrict__ qlist, float* __restrict__ out)
{
    int cls = blockIdx.x >> 4;
    int qt  = blockIdx.x & 15;
    int h   = blockIdx.y;
    int nQ = qcount[cls];
    if (qt * 64 >= nQ) return;
    int nK = kcount[cls];
    int ntiles = (nK + 63) >> 6;
    int nsplits = (ntiles + SPLIT_TILES - 1) / SPLIT_TILES;

    int tid = threadIdx.x;
    int grp = tid >> 2, lane4 = tid & 3;
    int qslot = qt * 64 + grp;
    if (qslot >= nQ) return;
    int row = qlist[cls * N_TOK + qslot];
    size_t slot = (size_t)h * SLOT_TOT + cls * QSLOTS + qslot;

    float L = 0.f;
    float Od[10];
    #pragma unroll
    for (int i = 0; i < 10; ++i) Od[i] = 0.f;

    for (int s = 0; s < nsplits; ++s) {
        size_t ps = slot * NSPLIT_MAX + s;
        L += pl[ps];
        const float* op = pO + ps * DH + lane4 * 10;
        #pragma unroll
        for (int i = 0; i < 5; ++i) {
            float2 t = *(const float2*)(op + 2*i);
            Od[2*i]   += t.x;
            Od[2*i+1] += t.y;
        }
    }
    float inv = 1.f / L;
    float* dst = &out[row * D_MODEL + h * DH + lane4 * 10];
    #pragma unroll
    for (int i = 0; i < 5; ++i)
        *(float2*)(dst + 2*i) = make_float2(Od[2*i] * inv, Od[2*i+1] * inv);
}

extern "C" void kernel_launch(void* const* d_in, const int* in_sizes, int n_in,
                              void* d_out, int out_size) {
    const float* x     = (const float*)d_in[0];
    const float* gmask = (const float*)d_in[1];
    const float* Wq    = (const float*)d_in[2];
    const float* Wk    = (const float*)d_in[3];
    const float* Wv    = (const float*)d_in[4];
    const float* Wo    = (const float*)d_in[5];
    const float* bo    = (const float*)d_in[6];
    float* out = (float*)d_out;

    float *Qp, *Vp, *Ap, *vmp, *pp, *plp, *pOp; __half* Khp;
    int *cp, *klp, *kcp, *qlp, *qcp;
    cudaGetSymbolAddress((void**)&Qp, g_Q);
    cudaGetSymbolAddress((void**)&Khp, g_Kh);
    cudaGetSymbolAddress((void**)&Vp, g_V);
    cudaGetSymbolAddress((void**)&Ap, g_A);
    cudaGetSymbolAddress((void**)&vmp, g_vmean);
    cudaGetSymbolAddress((void**)&pp, g_part);
    cudaGetSymbolAddress((void**)&cp, g_code);
    cudaGetSymbolAddress((void**)&klp, g_klist);
    cudaGetSymbolAddress((void**)&kcp, g_kcount);
    cudaGetSymbolAddress((void**)&qlp, g_qlist);
    cudaGetSymbolAddress((void**)&qcp, g_qcount);
    cudaGetSymbolAddress((void**)&plp, g_pl);
    cudaGetSymbolAddress((void**)&pOp, g_pO);

    code_kernel<<<16, 256>>>(gmask, cp);
    build_lists<<<7, 256>>>(cp, klp, kcp, qlp, qcp);
    gemm64_qkv<<<dim3(D_MODEL / 64, N_TOK / 64, 3), 256>>>(x, Wq, Wk, Wv, Qp, Khp, Vp);
    attn_kernel<<<dim3(7 * 16, HEADS, NSPLIT_MAX), 128>>>(
        Qp, Khp, Vp, klp, kcp, qlp, qcp, plp, pOp);
    merge_attn<<<dim3(7 * 16, HEADS), 256>>>(plp, pOp, kcp, qcp, qlp, Ap);
    vmean1<<<32, 320>>>(Vp, pp);
    vmean2<<<1, 320>>>(pp, vmp);
    fill_inactive<<<N_TOK, 64>>>(cp, vmp, Ap);
    gemm64<<<dim3(D_MODEL / 64, N_TOK / 64), 256>>>(Ap, Wo, bo, out, N_TOK, D_MODEL, D_MODEL);
}